// round 11
// baseline (speedup 1.0000x reference)
#include <cuda_runtime.h>
#include <cuda_bf16.h>
#include <math.h>
#include <stdint.h>

#define BB 16
#define GG 4
#define CGc 64
#define HH 64
#define WW 64
#define HWs 4096
#define KK 9

// ---------------- scratch (static; no allocation) ----------------
__device__ float g_off[BB*GG*18*HWs];                 // offsets [bg][c=2k+j][h][w]
__device__ float2 g_xP[BB*GG*CGc*HWs];                // x pairs: [bg][ic][y][x] = (v[x], v[x+1])  (134MB)
__device__ __nv_bfloat16 g_wbh[GG*KK*CGc*CGc];        // def_w bf16 hi, pre-SW128-swizzled rows [oc][ic]
__device__ __nv_bfloat16 g_wbl[GG*KK*CGc*CGc];        // def_w bf16 lo, same layout
__device__ __nv_bfloat16 g_owbh[GG*KK*32*CGc];        // off_w bf16 hi, SW128 rows [oc(32 pad)][ic]
__device__ __nv_bfloat16 g_owbl[GG*KK*32*CGc];        // off_w bf16 lo

#define SWZ128(off) ((off) ^ (((off) >> 3) & 0x70))

// ---------------- helpers ----------------
__device__ __forceinline__ uint32_t smem_u32(const void* p) {
    uint32_t a;
    asm("{ .reg .u64 t; cvta.to.shared.u64 t, %1; cvt.u32.u64 %0, t; }" : "=r"(a) : "l"(p));
    return a;
}
__device__ __forceinline__ void ldsm_x4(uint32_t* r, uint32_t addr) {
    asm volatile("ldmatrix.sync.aligned.m8n8.x4.shared.b16 {%0,%1,%2,%3}, [%4];"
        : "=r"(r[0]), "=r"(r[1]), "=r"(r[2]), "=r"(r[3]) : "r"(addr));
}
__device__ __forceinline__ void mma_bf16(float* d, const uint32_t* a, uint32_t b0, uint32_t b1) {
    asm volatile(
        "mma.sync.aligned.m16n8k16.row.col.f32.bf16.bf16.f32 "
        "{%0,%1,%2,%3}, {%4,%5,%6,%7}, {%8,%9}, {%0,%1,%2,%3};"
        : "+f"(d[0]), "+f"(d[1]), "+f"(d[2]), "+f"(d[3])
        : "r"(a[0]), "r"(a[1]), "r"(a[2]), "r"(a[3]), "r"(b0), "r"(b1));
}

// ---------------- prep: weight transforms ----------------
__global__ void prep_kernel(const float* __restrict__ off_w,
                            const float* __restrict__ def_w) {
    int idx = blockIdx.x * blockDim.x + threadIdx.x;
    const int n_w = GG*KK*CGc*CGc;    // 147456
    if (idx < n_w) {
        int ic = idx & 63;
        int oc = (idx >> 6) & 63;
        int gk = idx >> 12;           // g*9+k
        int k  = gk % KK;
        int g  = gk / KK;
        float w = def_w[((g*CGc + oc)*CGc + ic)*KK + k];
        __nv_bfloat16 hi = __float2bfloat16(w);
        float lo = w - __bfloat162float(hi);
        uint32_t sw = SWZ128((uint32_t)(oc*128 + ic*2));
        size_t base = (size_t)(g*KK + k) * CGc * CGc;
        g_wbh[base + sw/2] = hi;
        g_wbl[base + sw/2] = __float2bfloat16(lo);
    }
    const int n_ow = GG*KK*32*CGc;    // 73728  offset-conv weights, oc padded to 32
    if (idx < n_ow) {
        int ic = idx & 63;
        int oc = (idx >> 6) & 31;
        int gk = idx >> 11;           // g*9+k
        int k  = gk % KK;
        int g  = gk / KK;
        float w = (oc < 18) ? off_w[((g*18 + oc)*CGc + ic)*KK + k] : 0.0f;
        __nv_bfloat16 hi = __float2bfloat16(w);
        float lo = w - __bfloat162float(hi);
        uint32_t sw = SWZ128((uint32_t)(oc*128 + ic*2));
        size_t base = (size_t)(g*KK + k) * 32 * CGc;
        g_owbh[base + sw/2] = hi;
        g_owbl[base + sw/2] = __float2bfloat16(lo);
    }
}

// ---------------- pair build: xP[i] = (x[i], x[i+1 or clamp]) ----------------
__global__ void __launch_bounds__(256) pair_kernel(const float* __restrict__ x) {
    size_t i = (size_t)blockIdx.x * 256 + threadIdx.x;   // over BB*GG*CGc*HWs
    int xc = (int)(i & 63);
    float v  = x[i];
    float vn = (xc < 63) ? x[i + 1] : v;
    g_xP[i] = make_float2(v, vn);
}

// ---------------- offset conv via mma.sync: 64 -> 18(pad 32), 3x3 (UNCHANGED R10) ----------------
#define OSM_SHI  0
#define OSM_SLO  32768
#define OSM_WHI  65536
#define OSM_WLO  69632
#define OSM_TOTAL 73728

extern __shared__ char osmem[];
__global__ void __launch_bounds__(256) offset_mma_kernel(const float* __restrict__ x,
                                                         const float* __restrict__ off_b) {
    char* sm = osmem;
    uint32_t smem_base = smem_u32(sm);
    int tid  = threadIdx.x;
    int wid  = tid >> 5;
    int lane = tid & 31;

    int bid  = blockIdx.x;
    int hblk = bid & 15;
    int g    = (bid >> 4) & 3;
    int b    = bid >> 6;
    int bg   = b*GG + g;

    int m    = tid;
    int r    = m >> 6;
    int wpos = m & 63;
    int h    = hblk*4 + r;

    const float* xb = x + (size_t)bg * CGc * HWs;

    char* shi_row = sm + OSM_SHI + m*128;
    char* slo_row = sm + OSM_SLO + m*128;
    uint32_t swz = (uint32_t)((m & 7) << 4);

    float acc[2][4][4];
#pragma unroll
    for (int mt = 0; mt < 2; mt++)
#pragma unroll
        for (int nt = 0; nt < 4; nt++)
#pragma unroll
            for (int q = 0; q < 4; q++) acc[mt][nt][q] = 0.0f;

    int a_row0   = wid*32 + (lane & 15);
    int ab_colsl = (lane >> 4) << 4;
    int b_row0   = ((lane >> 3) & 1)*8 + (lane & 7);

    for (int k = 0; k < KK; k++) {
        {
            const uint4* s1 = (const uint4*)(g_owbh + (size_t)(g*KK + k) * 32 * CGc);
            const uint4* s2 = (const uint4*)(g_owbl + (size_t)(g*KK + k) * 32 * CGc);
            ((uint4*)(sm + OSM_WHI))[tid] = s1[tid];
            ((uint4*)(sm + OSM_WLO))[tid] = s2[tid];
        }

        int dy = k/3 - 1, dx = k%3 - 1;
        int y    = h + dy;
        int xcol = wpos + dx;
        bool valid = (y >= 0 && y < HH && xcol >= 0 && xcol < WW);
        const float* xs = xb + y*WW + xcol;
#pragma unroll
        for (int icp = 0; icp < 8; icp++) {
            uint32_t hp[4], lp[4];
#pragma unroll
            for (int jj = 0; jj < 2; jj++) {
                int ic = icp*8 + jj*4;
                float v0 = valid ? __ldg(xs + (size_t)(ic  )*HWs) : 0.0f;
                float v1 = valid ? __ldg(xs + (size_t)(ic+1)*HWs) : 0.0f;
                float v2 = valid ? __ldg(xs + (size_t)(ic+2)*HWs) : 0.0f;
                float v3 = valid ? __ldg(xs + (size_t)(ic+3)*HWs) : 0.0f;
                uint32_t hh0, hh1;
                asm("cvt.rn.bf16x2.f32 %0, %1, %2;" : "=r"(hh0) : "f"(v1), "f"(v0));
                asm("cvt.rn.bf16x2.f32 %0, %1, %2;" : "=r"(hh1) : "f"(v3), "f"(v2));
                float l0 = v0 - __uint_as_float(hh0 << 16);
                float l1 = v1 - __uint_as_float(hh0 & 0xffff0000u);
                float l2 = v2 - __uint_as_float(hh1 << 16);
                float l3 = v3 - __uint_as_float(hh1 & 0xffff0000u);
                uint32_t ll0, ll1;
                asm("cvt.rn.bf16x2.f32 %0, %1, %2;" : "=r"(ll0) : "f"(l1), "f"(l0));
                asm("cvt.rn.bf16x2.f32 %0, %1, %2;" : "=r"(ll1) : "f"(l3), "f"(l2));
                hp[2*jj] = hh0; hp[2*jj+1] = hh1;
                lp[2*jj] = ll0; lp[2*jj+1] = ll1;
            }
            uint32_t off = ((uint32_t)(icp*16)) ^ swz;
            *(uint4*)(shi_row + off) = make_uint4(hp[0], hp[1], hp[2], hp[3]);
            *(uint4*)(slo_row + off) = make_uint4(lp[0], lp[1], lp[2], lp[3]);
        }
        __syncthreads();

#pragma unroll
        for (int kc = 0; kc < 4; kc++) {
            int colb = kc*32 + ab_colsl;
            uint32_t ah[2][4], al[2][4];
#pragma unroll
            for (int mt = 0; mt < 2; mt++) {
                int row = a_row0 + mt*16;
                uint32_t boff = (uint32_t)(row*128 + (colb ^ ((row & 7) << 4)));
                ldsm_x4(ah[mt], smem_base + OSM_SHI + boff);
                ldsm_x4(al[mt], smem_base + OSM_SLO + boff);
            }
#pragma unroll
            for (int ntp = 0; ntp < 2; ntp++) {
                int nrow = b_row0 + ntp*16;
                uint32_t boff = (uint32_t)(nrow*128 + (colb ^ ((nrow & 7) << 4)));
                uint32_t bh[4], bl[4];
                ldsm_x4(bh, smem_base + OSM_WHI + boff);
                ldsm_x4(bl, smem_base + OSM_WLO + boff);
#pragma unroll
                for (int mt = 0; mt < 2; mt++) {
                    mma_bf16(acc[mt][2*ntp  ], ah[mt], bh[0], bh[2]);
                    mma_bf16(acc[mt][2*ntp  ], ah[mt], bl[0], bl[2]);
                    mma_bf16(acc[mt][2*ntp  ], al[mt], bh[0], bh[2]);
                    mma_bf16(acc[mt][2*ntp+1], ah[mt], bh[1], bh[3]);
                    mma_bf16(acc[mt][2*ntp+1], ah[mt], bl[1], bl[3]);
                    mma_bf16(acc[mt][2*ntp+1], al[mt], bh[1], bh[3]);
                }
            }
        }
        __syncthreads();
    }

    float* og = g_off + (size_t)bg * 18 * HWs + hblk*4*64;
    const float* obp = off_b + g*18;
#pragma unroll
    for (int mt = 0; mt < 2; mt++) {
        int row0  = wid*32 + mt*16 + (lane >> 2);
        int h_loc = row0 >> 6;
        int wp    = row0 & 63;
        float* p0 = og + h_loc*64 + wp;
        float* p1 = p0 + 8;
#pragma unroll
        for (int nt = 0; nt < 4; nt++) {
            int c0 = nt*8 + (lane & 3)*2;
            if (c0 < 18) {
                float bz0 = __ldg(obp + c0);
                float bz1 = __ldg(obp + c0 + 1);
                p0[(size_t)c0*HWs]     = acc[mt][nt][0] + bz0;
                p0[(size_t)(c0+1)*HWs] = acc[mt][nt][1] + bz1;
                p1[(size_t)c0*HWs]     = acc[mt][nt][2] + bz0;
                p1[(size_t)(c0+1)*HWs] = acc[mt][nt][3] + bz1;
            }
        }
    }
}

// ---------------- deformable conv: mma.sync bf16x2 GEMM ----------------
// block = (b, g, hblk of 4 rows); 512 threads (16 warps), 2 blocks/SM
// M=256 (4h x 64w), N=64 oc, K per tap = 64 ic, 9 taps
// Each thread gathers HALF a row (32 channels); each warp owns ONE 16-row m-tile.
#define SM_SHI  0        // S hi [256 x 64] bf16 SW128 : 32768 B
#define SM_SLO  32768    // S lo                       : 32768 B
#define SM_WHI  65536    // W hi [64 x 64] bf16 SW128  :  8192 B
#define SM_WLO  73728    // W lo                       :  8192 B
#define SM_TOTAL 81920

extern __shared__ char smem2[];
__global__ void __launch_bounds__(512, 2) deform_kernel(const float* __restrict__ def_b,
                                                        float* __restrict__ out) {
    char* sm = smem2;
    uint32_t smem_base = smem_u32(sm);
    int tid  = threadIdx.x;
    int wid  = tid >> 5;       // 0..15
    int lane = tid & 31;

    int bid  = blockIdx.x;
    int hblk = bid & 15;
    int g    = (bid >> 4) & 3;
    int b    = bid >> 6;
    int bg   = b*GG + g;

    int row  = tid >> 1;       // S-tile row this thread helps gather (0..255)
    int ich  = (tid & 1) * 32; // channel half
    int r    = row >> 6;       // 0..3
    int wpos = row & 63;
    int h    = hblk*4 + r;

    const float2* xPb = g_xP + (size_t)bg * CGc * HWs;
    const float* offp = g_off + (size_t)bg * 18 * HWs + h*64 + wpos;

    char* shi_row = sm + SM_SHI + row*128;
    char* slo_row = sm + SM_SLO + row*128;
    uint32_t swz = (uint32_t)((row & 7) << 4);

    float acc[8][4];
#pragma unroll
    for (int nt = 0; nt < 8; nt++)
#pragma unroll
        for (int q = 0; q < 4; q++) acc[nt][q] = 0.0f;

    // per-thread ldmatrix row/col components (1 m-tile per warp)
    int a_row0   = wid*16 + (lane & 15);
    int ab_colsl = (lane >> 4) << 4;
    int b_row0   = ((lane >> 3) & 1)*8 + (lane & 7);

    for (int k = 0; k < KK; k++) {
        // ---- fill W tiles (pre-swizzled gmem -> linear copy; 512 thr x 1 uint4 each) ----
        {
            const uint4* s1 = (const uint4*)(g_wbh + (size_t)(g*KK + k) * CGc * CGc);
            const uint4* s2 = (const uint4*)(g_wbl + (size_t)(g*KK + k) * CGc * CGc);
            ((uint4*)(sm + SM_WHI))[tid] = s1[tid];
            ((uint4*)(sm + SM_WLO))[tid] = s2[tid];
        }

        // ---- per-thread bilinear corner precompute (both row-halves duplicate it) ----
        float dy = __ldg(offp + (2*k    )*HWs);
        float dx = __ldg(offp + (2*k + 1)*HWs);
        float py = dy + (float)(k/3 - 1) + (float)h;
        float px = dx + (float)(k%3 - 1) + (float)wpos;
        float fy = floorf(py), fx = floorf(px);
        float wy = py - fy,    wx = px - fx;
        int y0 = (int)fy, x0 = (int)fx;
        int y1 = y0 + 1,  x1 = x0 + 1;
        float vy0 = (y0 >= 0 && y0 < HH) ? 1.f : 0.f;
        float vy1 = (y1 >= 0 && y1 < HH) ? 1.f : 0.f;
        float vx0 = (x0 >= 0 && x0 < WW) ? 1.f : 0.f;
        float vx1 = (x1 >= 0 && x1 < WW) ? 1.f : 0.f;
        float c00 = (1.f-wy)*(1.f-wx) * vy0 * vx0;
        float c01 = (1.f-wy)*wx       * vy0 * vx1;
        float c10 = wy*(1.f-wx)       * vy1 * vx0;
        float c11 = wy*wx             * vy1 * vx1;
        if (x0 < 0) { c00 = c01; c01 = 0.f; c10 = c11; c11 = 0.f; }
        int xl  = min(max(x0,0),WW-1);
        int y0c = min(max(y0,0),HH-1), y1c = min(max(y1,0),HH-1);
        int o0 = y0c*WW + xl;
        int o1 = y1c*WW + xl;

        // ---- gather (paired LDG.64) + bf16 hi/lo split; 32 channels per thread ----
#pragma unroll
        for (int icp = 0; icp < 4; icp++) {
            uint32_t hp[4], lp[4];
#pragma unroll
            for (int jj = 0; jj < 2; jj++) {
                int ic = ich + icp*8 + jj*4;
                float2 a0 = __ldg(xPb + (size_t)ic*HWs + o0);
                float2 a1 = __ldg(xPb + (size_t)ic*HWs + o1);
                float2 b0 = __ldg(xPb + (size_t)(ic+1)*HWs + o0);
                float2 b1 = __ldg(xPb + (size_t)(ic+1)*HWs + o1);
                float2 e0 = __ldg(xPb + (size_t)(ic+2)*HWs + o0);
                float2 e1 = __ldg(xPb + (size_t)(ic+2)*HWs + o1);
                float2 f0 = __ldg(xPb + (size_t)(ic+3)*HWs + o0);
                float2 f1 = __ldg(xPb + (size_t)(ic+3)*HWs + o1);
                float v0 = c00*a0.x + c01*a0.y + c10*a1.x + c11*a1.y;
                float v1 = c00*b0.x + c01*b0.y + c10*b1.x + c11*b1.y;
                float v2 = c00*e0.x + c01*e0.y + c10*e1.x + c11*e1.y;
                float v3 = c00*f0.x + c01*f0.y + c10*f1.x + c11*f1.y;
                uint32_t hh0, hh1;
                asm("cvt.rn.bf16x2.f32 %0, %1, %2;" : "=r"(hh0) : "f"(v1), "f"(v0));
                asm("cvt.rn.bf16x2.f32 %0, %1, %2;" : "=r"(hh1) : "f"(v3), "f"(v2));
                float l0 = v0 - __uint_as_float(hh0 << 16);
                float l1 = v1 - __uint_as_float(hh0 & 0xffff0000u);
                float l2 = v2 - __uint_as_float(hh1 << 16);
                float l3 = v3 - __uint_as_float(hh1 & 0xffff0000u);
                uint32_t ll0, ll1;
                asm("cvt.rn.bf16x2.f32 %0, %1, %2;" : "=r"(ll0) : "f"(l1), "f"(l0));
                asm("cvt.rn.bf16x2.f32 %0, %1, %2;" : "=r"(ll1) : "f"(l3), "f"(l2));
                hp[2*jj] = hh0; hp[2*jj+1] = hh1;
                lp[2*jj] = ll0; lp[2*jj+1] = ll1;
            }
            uint32_t off = ((uint32_t)(ich*2 + icp*16)) ^ swz;
            *(uint4*)(shi_row + off) = make_uint4(hp[0], hp[1], hp[2], hp[3]);
            *(uint4*)(slo_row + off) = make_uint4(lp[0], lp[1], lp[2], lp[3]);
        }
        __syncthreads();

        // ---- MMA: 4 k16-chunks x (1 m-tile x 8 n-tiles) x 3 bf16x2 terms ----
#pragma unroll
        for (int kc = 0; kc < 4; kc++) {
            int colb = kc*32 + ab_colsl;
            uint32_t ah[4], al[4];
            {
                int arow = a_row0;
                uint32_t boff = (uint32_t)(arow*128 + (colb ^ ((arow & 7) << 4)));
                ldsm_x4(ah, smem_base + SM_SHI + boff);
                ldsm_x4(al, smem_base + SM_SLO + boff);
            }
#pragma unroll
            for (int ntp = 0; ntp < 4; ntp++) {
                int nrow = b_row0 + ntp*16;
                uint32_t boff = (uint32_t)(nrow*128 + (colb ^ ((nrow & 7) << 4)));
                uint32_t bh[4], bl[4];
                ldsm_x4(bh, smem_base + SM_WHI + boff);
                ldsm_x4(bl, smem_base + SM_WLO + boff);
                mma_bf16(acc[2*ntp  ], ah, bh[0], bh[2]);
                mma_bf16(acc[2*ntp  ], ah, bl[0], bl[2]);
                mma_bf16(acc[2*ntp  ], al, bh[0], bh[2]);
                mma_bf16(acc[2*ntp+1], ah, bh[1], bh[3]);
                mma_bf16(acc[2*ntp+1], ah, bl[1], bl[3]);
                mma_bf16(acc[2*ntp+1], al, bh[1], bh[3]);
            }
        }
        __syncthreads();   // all warps done reading S/W before next tap overwrites
    }

    // ---- epilogue: fragment scatter to gmem (+bias) ----
    float* outg = out + (size_t)bg * CGc * HWs + hblk*4*64;
    const float* bbp = def_b + g*CGc;
    {
        int row0  = wid*16 + (lane >> 2);
        int h_loc = row0 >> 6;
        int wp    = row0 & 63;
        float* p0 = outg + h_loc*64 + wp;
        float* p1 = p0 + 8;   // row0+8 stays in same 64-row band
#pragma unroll
        for (int nt = 0; nt < 8; nt++) {
            int oc0 = nt*8 + (lane & 3)*2;
            float bz0 = __ldg(bbp + oc0);
            float bz1 = __ldg(bbp + oc0 + 1);
            p0[(size_t)oc0*HWs]       = acc[nt][0] + bz0;
            p0[(size_t)(oc0+1)*HWs]   = acc[nt][1] + bz1;
            p1[(size_t)oc0*HWs]       = acc[nt][2] + bz0;
            p1[(size_t)(oc0+1)*HWs]   = acc[nt][3] + bz1;
        }
    }
}

// ---------------- launch ----------------
extern "C" void kernel_launch(void* const* d_in, const int* in_sizes, int n_in,
                              void* d_out, int out_size) {
    const float* x     = (const float*)d_in[0];
    const float* off_w = (const float*)d_in[1];
    const float* off_b = (const float*)d_in[2];
    const float* def_w = (const float*)d_in[3];
    const float* def_b = (const float*)d_in[4];
    float* out = (float*)d_out;

    cudaFuncSetAttribute(offset_mma_kernel, cudaFuncAttributeMaxDynamicSharedMemorySize,
                         OSM_TOTAL);                              // 73728 B
    cudaFuncSetAttribute(deform_kernel, cudaFuncAttributeMaxDynamicSharedMemorySize,
                         SM_TOTAL);                               // 81920 B

    prep_kernel<<<(GG*KK*CGc*CGc + 255) / 256, 256>>>(off_w, def_w);
    pair_kernel<<<BB*GG*CGc*HWs/256, 256>>>(x);
    offset_mma_kernel<<<BB*GG*(HH/4), 256, OSM_TOTAL>>>(x, off_b);
    deform_kernel<<<BB*GG*(HH/4), 512, SM_TOTAL>>>(def_b, out);
}

// round 13
// speedup vs baseline: 1.0911x; 1.0911x over previous
#include <cuda_runtime.h>
#include <cuda_bf16.h>
#include <math.h>
#include <stdint.h>

#define BB 16
#define GG 4
#define CGc 64
#define HH 64
#define WW 64
#define HWs 4096
#define KK 9

// ---------------- scratch (static; no allocation) ----------------
__device__ float g_off[BB*GG*18*HWs];                 // offsets [bg][c=2k+j][h][w]
__device__ float4 g_xQ[BB*GG*CGc*HWs];                // corner quads: (v[y][x], v[y][x+1], v[y+1][x], v[y+1][x+1])  (268MB)
__device__ __nv_bfloat16 g_wbh[GG*KK*CGc*CGc];        // def_w bf16 hi, pre-SW128-swizzled rows [oc][ic]
__device__ __nv_bfloat16 g_wbl[GG*KK*CGc*CGc];        // def_w bf16 lo, same layout
__device__ __nv_bfloat16 g_owbh[GG*KK*32*CGc];        // off_w bf16 hi, SW128 rows [oc(32 pad)][ic]
__device__ __nv_bfloat16 g_owbl[GG*KK*32*CGc];        // off_w bf16 lo

#define SWZ128(off) ((off) ^ (((off) >> 3) & 0x70))

// ---------------- helpers ----------------
__device__ __forceinline__ uint32_t smem_u32(const void* p) {
    uint32_t a;
    asm("{ .reg .u64 t; cvta.to.shared.u64 t, %1; cvt.u32.u64 %0, t; }" : "=r"(a) : "l"(p));
    return a;
}
__device__ __forceinline__ void ldsm_x4(uint32_t* r, uint32_t addr) {
    asm volatile("ldmatrix.sync.aligned.m8n8.x4.shared.b16 {%0,%1,%2,%3}, [%4];"
        : "=r"(r[0]), "=r"(r[1]), "=r"(r[2]), "=r"(r[3]) : "r"(addr));
}
__device__ __forceinline__ void mma_bf16(float* d, const uint32_t* a, uint32_t b0, uint32_t b1) {
    asm volatile(
        "mma.sync.aligned.m16n8k16.row.col.f32.bf16.bf16.f32 "
        "{%0,%1,%2,%3}, {%4,%5,%6,%7}, {%8,%9}, {%0,%1,%2,%3};"
        : "+f"(d[0]), "+f"(d[1]), "+f"(d[2]), "+f"(d[3])
        : "r"(a[0]), "r"(a[1]), "r"(a[2]), "r"(a[3]), "r"(b0), "r"(b1));
}

// ---------------- prep: weight transforms ----------------
__global__ void prep_kernel(const float* __restrict__ off_w,
                            const float* __restrict__ def_w) {
    int idx = blockIdx.x * blockDim.x + threadIdx.x;
    const int n_w = GG*KK*CGc*CGc;    // 147456
    if (idx < n_w) {
        int ic = idx & 63;
        int oc = (idx >> 6) & 63;
        int gk = idx >> 12;           // g*9+k
        int k  = gk % KK;
        int g  = gk / KK;
        float w = def_w[((g*CGc + oc)*CGc + ic)*KK + k];
        __nv_bfloat16 hi = __float2bfloat16(w);
        float lo = w - __bfloat162float(hi);
        uint32_t sw = SWZ128((uint32_t)(oc*128 + ic*2));
        size_t base = (size_t)(g*KK + k) * CGc * CGc;
        g_wbh[base + sw/2] = hi;
        g_wbl[base + sw/2] = __float2bfloat16(lo);
    }
    const int n_ow = GG*KK*32*CGc;    // 73728  offset-conv weights, oc padded to 32
    if (idx < n_ow) {
        int ic = idx & 63;
        int oc = (idx >> 6) & 31;
        int gk = idx >> 11;           // g*9+k
        int k  = gk % KK;
        int g  = gk / KK;
        float w = (oc < 18) ? off_w[((g*18 + oc)*CGc + ic)*KK + k] : 0.0f;
        __nv_bfloat16 hi = __float2bfloat16(w);
        float lo = w - __bfloat162float(hi);
        uint32_t sw = SWZ128((uint32_t)(oc*128 + ic*2));
        size_t base = (size_t)(g*KK + k) * 32 * CGc;
        g_owbh[base + sw/2] = hi;
        g_owbl[base + sw/2] = __float2bfloat16(lo);
    }
}

// ---------------- quad build: all 4 bilinear corners in one float4 ----------------
__global__ void __launch_bounds__(256) quad_kernel(const float* __restrict__ x) {
    size_t i = (size_t)blockIdx.x * 256 + threadIdx.x;   // over BB*GG*CGc*HWs
    int xc = (int)(i & 63);
    int yc = (int)((i >> 6) & 63);
    float v00 = x[i];
    float v01 = (xc < 63) ? x[i + 1]  : v00;
    float v10 = (yc < 63) ? x[i + 64] : v00;
    float v11 = (yc < 63) ? ((xc < 63) ? x[i + 65] : v10) : v01;
    g_xQ[i] = make_float4(v00, v01, v10, v11);
}

// ---------------- offset conv via mma.sync: 64 -> 18(pad 32), 3x3 (UNCHANGED R10) ----------------
#define OSM_SHI  0
#define OSM_SLO  32768
#define OSM_WHI  65536
#define OSM_WLO  69632
#define OSM_TOTAL 73728

extern __shared__ char osmem[];
__global__ void __launch_bounds__(256) offset_mma_kernel(const float* __restrict__ x,
                                                         const float* __restrict__ off_b) {
    char* sm = osmem;
    uint32_t smem_base = smem_u32(sm);
    int tid  = threadIdx.x;
    int wid  = tid >> 5;
    int lane = tid & 31;

    int bid  = blockIdx.x;
    int hblk = bid & 15;
    int g    = (bid >> 4) & 3;
    int b    = bid >> 6;
    int bg   = b*GG + g;

    int m    = tid;
    int r    = m >> 6;
    int wpos = m & 63;
    int h    = hblk*4 + r;

    const float* xb = x + (size_t)bg * CGc * HWs;

    char* shi_row = sm + OSM_SHI + m*128;
    char* slo_row = sm + OSM_SLO + m*128;
    uint32_t swz = (uint32_t)((m & 7) << 4);

    float acc[2][4][4];
#pragma unroll
    for (int mt = 0; mt < 2; mt++)
#pragma unroll
        for (int nt = 0; nt < 4; nt++)
#pragma unroll
            for (int q = 0; q < 4; q++) acc[mt][nt][q] = 0.0f;

    int a_row0   = wid*32 + (lane & 15);
    int ab_colsl = (lane >> 4) << 4;
    int b_row0   = ((lane >> 3) & 1)*8 + (lane & 7);

    for (int k = 0; k < KK; k++) {
        {
            const uint4* s1 = (const uint4*)(g_owbh + (size_t)(g*KK + k) * 32 * CGc);
            const uint4* s2 = (const uint4*)(g_owbl + (size_t)(g*KK + k) * 32 * CGc);
            ((uint4*)(sm + OSM_WHI))[tid] = s1[tid];
            ((uint4*)(sm + OSM_WLO))[tid] = s2[tid];
        }

        int dy = k/3 - 1, dx = k%3 - 1;
        int y    = h + dy;
        int xcol = wpos + dx;
        bool valid = (y >= 0 && y < HH && xcol >= 0 && xcol < WW);
        const float* xs = xb + y*WW + xcol;
#pragma unroll
        for (int icp = 0; icp < 8; icp++) {
            uint32_t hp[4], lp[4];
#pragma unroll
            for (int jj = 0; jj < 2; jj++) {
                int ic = icp*8 + jj*4;
                float v0 = valid ? __ldg(xs + (size_t)(ic  )*HWs) : 0.0f;
                float v1 = valid ? __ldg(xs + (size_t)(ic+1)*HWs) : 0.0f;
                float v2 = valid ? __ldg(xs + (size_t)(ic+2)*HWs) : 0.0f;
                float v3 = valid ? __ldg(xs + (size_t)(ic+3)*HWs) : 0.0f;
                uint32_t hh0, hh1;
                asm("cvt.rn.bf16x2.f32 %0, %1, %2;" : "=r"(hh0) : "f"(v1), "f"(v0));
                asm("cvt.rn.bf16x2.f32 %0, %1, %2;" : "=r"(hh1) : "f"(v3), "f"(v2));
                float l0 = v0 - __uint_as_float(hh0 << 16);
                float l1 = v1 - __uint_as_float(hh0 & 0xffff0000u);
                float l2 = v2 - __uint_as_float(hh1 << 16);
                float l3 = v3 - __uint_as_float(hh1 & 0xffff0000u);
                uint32_t ll0, ll1;
                asm("cvt.rn.bf16x2.f32 %0, %1, %2;" : "=r"(ll0) : "f"(l1), "f"(l0));
                asm("cvt.rn.bf16x2.f32 %0, %1, %2;" : "=r"(ll1) : "f"(l3), "f"(l2));
                hp[2*jj] = hh0; hp[2*jj+1] = hh1;
                lp[2*jj] = ll0; lp[2*jj+1] = ll1;
            }
            uint32_t off = ((uint32_t)(icp*16)) ^ swz;
            *(uint4*)(shi_row + off) = make_uint4(hp[0], hp[1], hp[2], hp[3]);
            *(uint4*)(slo_row + off) = make_uint4(lp[0], lp[1], lp[2], lp[3]);
        }
        __syncthreads();

#pragma unroll
        for (int kc = 0; kc < 4; kc++) {
            int colb = kc*32 + ab_colsl;
            uint32_t ah[2][4], al[2][4];
#pragma unroll
            for (int mt = 0; mt < 2; mt++) {
                int row = a_row0 + mt*16;
                uint32_t boff = (uint32_t)(row*128 + (colb ^ ((row & 7) << 4)));
                ldsm_x4(ah[mt], smem_base + OSM_SHI + boff);
                ldsm_x4(al[mt], smem_base + OSM_SLO + boff);
            }
#pragma unroll
            for (int ntp = 0; ntp < 2; ntp++) {
                int nrow = b_row0 + ntp*16;
                uint32_t boff = (uint32_t)(nrow*128 + (colb ^ ((nrow & 7) << 4)));
                uint32_t bh[4], bl[4];
                ldsm_x4(bh, smem_base + OSM_WHI + boff);
                ldsm_x4(bl, smem_base + OSM_WLO + boff);
#pragma unroll
                for (int mt = 0; mt < 2; mt++) {
                    mma_bf16(acc[mt][2*ntp  ], ah[mt], bh[0], bh[2]);
                    mma_bf16(acc[mt][2*ntp  ], ah[mt], bl[0], bl[2]);
                    mma_bf16(acc[mt][2*ntp  ], al[mt], bh[0], bh[2]);
                    mma_bf16(acc[mt][2*ntp+1], ah[mt], bh[1], bh[3]);
                    mma_bf16(acc[mt][2*ntp+1], ah[mt], bl[1], bl[3]);
                    mma_bf16(acc[mt][2*ntp+1], al[mt], bh[1], bh[3]);
                }
            }
        }
        __syncthreads();
    }

    float* og = g_off + (size_t)bg * 18 * HWs + hblk*4*64;
    const float* obp = off_b + g*18;
#pragma unroll
    for (int mt = 0; mt < 2; mt++) {
        int row0  = wid*32 + mt*16 + (lane >> 2);
        int h_loc = row0 >> 6;
        int wp    = row0 & 63;
        float* p0 = og + h_loc*64 + wp;
        float* p1 = p0 + 8;
#pragma unroll
        for (int nt = 0; nt < 4; nt++) {
            int c0 = nt*8 + (lane & 3)*2;
            if (c0 < 18) {
                float bz0 = __ldg(obp + c0);
                float bz1 = __ldg(obp + c0 + 1);
                p0[(size_t)c0*HWs]     = acc[mt][nt][0] + bz0;
                p0[(size_t)(c0+1)*HWs] = acc[mt][nt][1] + bz1;
                p1[(size_t)c0*HWs]     = acc[mt][nt][2] + bz0;
                p1[(size_t)(c0+1)*HWs] = acc[mt][nt][3] + bz1;
            }
        }
    }
}

// ---------------- deformable conv: mma.sync bf16x2 GEMM (R10 shape + quad gather) ----------------
// block = (b, g, hblk of 4 rows); 256 threads (8 warps)
// M=256 (4h x 64w), N=64 oc, K per tap = 64 ic, 9 taps
#define SM_SHI  0        // S hi [256 x 64] bf16 SW128 : 32768 B
#define SM_SLO  32768    // S lo                       : 32768 B
#define SM_WHI  65536    // W hi [64 x 64] bf16 SW128  :  8192 B
#define SM_WLO  73728    // W lo                       :  8192 B
#define SM_TOTAL 81920

extern __shared__ char smem2[];
__global__ void __launch_bounds__(256) deform_kernel(const float* __restrict__ def_b,
                                                     float* __restrict__ out) {
    char* sm = smem2;
    uint32_t smem_base = smem_u32(sm);
    int tid  = threadIdx.x;
    int wid  = tid >> 5;
    int lane = tid & 31;

    int bid  = blockIdx.x;
    int hblk = bid & 15;
    int g    = (bid >> 4) & 3;
    int b    = bid >> 6;
    int bg   = b*GG + g;

    int m    = tid;            // S-tile row this thread gathers
    int r    = m >> 6;         // 0..3
    int wpos = m & 63;
    int h    = hblk*4 + r;

    const float4* xQb = g_xQ + (size_t)bg * CGc * HWs;
    const float* offp = g_off + (size_t)bg * 18 * HWs + h*64 + wpos;

    char* shi_row = sm + SM_SHI + m*128;
    char* slo_row = sm + SM_SLO + m*128;
    uint32_t swz = (uint32_t)((m & 7) << 4);

    float acc[2][8][4];
#pragma unroll
    for (int mt = 0; mt < 2; mt++)
#pragma unroll
        for (int nt = 0; nt < 8; nt++)
#pragma unroll
            for (int q = 0; q < 4; q++) acc[mt][nt][q] = 0.0f;

    int a_row0   = wid*32 + (lane & 15);
    int ab_colsl = (lane >> 4) << 4;
    int b_row0   = ((lane >> 3) & 1)*8 + (lane & 7);

    for (int k = 0; k < KK; k++) {
        // ---- fill W tiles (pre-swizzled gmem -> linear copy) ----
        {
            const uint4* s1 = (const uint4*)(g_wbh + (size_t)(g*KK + k) * CGc * CGc);
            const uint4* s2 = (const uint4*)(g_wbl + (size_t)(g*KK + k) * CGc * CGc);
            uint4* d1 = (uint4*)(sm + SM_WHI);
            uint4* d2 = (uint4*)(sm + SM_WLO);
#pragma unroll
            for (int i = 0; i < 2; i++) {
                d1[tid + i*256] = s1[tid + i*256];
                d2[tid + i*256] = s2[tid + i*256];
            }
        }

        // ---- per-thread bilinear corner precompute ----
        float dy = __ldg(offp + (2*k    )*HWs);
        float dx = __ldg(offp + (2*k + 1)*HWs);
        float py = dy + (float)(k/3 - 1) + (float)h;
        float px = dx + (float)(k%3 - 1) + (float)wpos;
        float fy = floorf(py), fx = floorf(px);
        float wy = py - fy,    wx = px - fx;
        int y0 = (int)fy, x0 = (int)fx;
        int y1 = y0 + 1,  x1 = x0 + 1;
        float vy0 = (y0 >= 0 && y0 < HH) ? 1.f : 0.f;
        float vy1 = (y1 >= 0 && y1 < HH) ? 1.f : 0.f;
        float vx0 = (x0 >= 0 && x0 < WW) ? 1.f : 0.f;
        float vx1 = (x1 >= 0 && x1 < WW) ? 1.f : 0.f;
        float c00 = (1.f-wy)*(1.f-wx) * vy0 * vx0;
        float c01 = (1.f-wy)*wx       * vy0 * vx1;
        float c10 = wy*(1.f-wx)       * vy1 * vx0;
        float c11 = wy*wx             * vy1 * vx1;
        // quad slot fixups: quad at (yb,xl) covers (yb,xl),(yb,xl+1),(yb+1,xl),(yb+1,xl+1)
        // x0<0: only x1(=0) possibly valid -> move both row weights onto .x/.z slots
        if (x0 < 0) { c00 = c01; c01 = 0.f; c10 = c11; c11 = 0.f; }
        // y0<0: only y1(=0) possibly valid -> move both col weights onto top-row slots
        if (y0 < 0) { c00 = c10; c01 = c11; c10 = 0.f; c11 = 0.f; }
        int xl = min(max(x0,0),WW-1);
        int yb = min(max(y0,0),HH-1);
        int o  = yb*WW + xl;

        // ---- gather (quad LDG.128) + bf16 hi/lo split into S tiles ----
#pragma unroll
        for (int icp = 0; icp < 8; icp++) {
            uint32_t hp[4], lp[4];
#pragma unroll
            for (int jj = 0; jj < 2; jj++) {
                int ic = icp*8 + jj*4;
                float4 q0 = __ldg(xQb + (size_t)ic*HWs + o);
                float4 q1 = __ldg(xQb + (size_t)(ic+1)*HWs + o);
                float4 q2 = __ldg(xQb + (size_t)(ic+2)*HWs + o);
                float4 q3 = __ldg(xQb + (size_t)(ic+3)*HWs + o);
                float v0 = c00*q0.x + c01*q0.y + c10*q0.z + c11*q0.w;
                float v1 = c00*q1.x + c01*q1.y + c10*q1.z + c11*q1.w;
                float v2 = c00*q2.x + c01*q2.y + c10*q2.z + c11*q2.w;
                float v3 = c00*q3.x + c01*q3.y + c10*q3.z + c11*q3.w;
                uint32_t hh0, hh1;
                asm("cvt.rn.bf16x2.f32 %0, %1, %2;" : "=r"(hh0) : "f"(v1), "f"(v0));
                asm("cvt.rn.bf16x2.f32 %0, %1, %2;" : "=r"(hh1) : "f"(v3), "f"(v2));
                float l0 = v0 - __uint_as_float(hh0 << 16);
                float l1 = v1 - __uint_as_float(hh0 & 0xffff0000u);
                float l2 = v2 - __uint_as_float(hh1 << 16);
                float l3 = v3 - __uint_as_float(hh1 & 0xffff0000u);
                uint32_t ll0, ll1;
                asm("cvt.rn.bf16x2.f32 %0, %1, %2;" : "=r"(ll0) : "f"(l1), "f"(l0));
                asm("cvt.rn.bf16x2.f32 %0, %1, %2;" : "=r"(ll1) : "f"(l3), "f"(l2));
                hp[2*jj] = hh0; hp[2*jj+1] = hh1;
                lp[2*jj] = ll0; lp[2*jj+1] = ll1;
            }
            uint32_t off = ((uint32_t)(icp*16)) ^ swz;
            *(uint4*)(shi_row + off) = make_uint4(hp[0], hp[1], hp[2], hp[3]);
            *(uint4*)(slo_row + off) = make_uint4(lp[0], lp[1], lp[2], lp[3]);
        }
        __syncthreads();

        // ---- MMA: 4 k16-chunks x (2 m-tiles x 8 n-tiles) x 3 bf16x2 terms ----
#pragma unroll
        for (int kc = 0; kc < 4; kc++) {
            int colb = kc*32 + ab_colsl;
            uint32_t ah[2][4], al[2][4];
#pragma unroll
            for (int mt = 0; mt < 2; mt++) {
                int row = a_row0 + mt*16;
                uint32_t boff = (uint32_t)(row*128 + (colb ^ ((row & 7) << 4)));
                ldsm_x4(ah[mt], smem_base + SM_SHI + boff);
                ldsm_x4(al[mt], smem_base + SM_SLO + boff);
            }
#pragma unroll
            for (int ntp = 0; ntp < 4; ntp++) {
                int nrow = b_row0 + ntp*16;
                uint32_t boff = (uint32_t)(nrow*128 + (colb ^ ((nrow & 7) << 4)));
                uint32_t bh[4], bl[4];
                ldsm_x4(bh, smem_base + SM_WHI + boff);
                ldsm_x4(bl, smem_base + SM_WLO + boff);
#pragma unroll
                for (int mt = 0; mt < 2; mt++) {
                    mma_bf16(acc[mt][2*ntp  ], ah[mt], bh[0], bh[2]);
                    mma_bf16(acc[mt][2*ntp  ], ah[mt], bl[0], bl[2]);
                    mma_bf16(acc[mt][2*ntp  ], al[mt], bh[0], bh[2]);
                    mma_bf16(acc[mt][2*ntp+1], ah[mt], bh[1], bh[3]);
                    mma_bf16(acc[mt][2*ntp+1], ah[mt], bl[1], bl[3]);
                    mma_bf16(acc[mt][2*ntp+1], al[mt], bh[1], bh[3]);
                }
            }
        }
        __syncthreads();
    }

    // ---- epilogue: fragment scatter to gmem (+bias) ----
    float* outg = out + (size_t)bg * CGc * HWs + hblk*4*64;
    const float* bbp = def_b + g*CGc;
#pragma unroll
    for (int mt = 0; mt < 2; mt++) {
        int row0  = wid*32 + mt*16 + (lane >> 2);
        int h_loc = row0 >> 6;
        int wp    = row0 & 63;
        float* p0 = outg + h_loc*64 + wp;
        float* p1 = p0 + 8;
#pragma unroll
        for (int nt = 0; nt < 8; nt++) {
            int oc0 = nt*8 + (lane & 3)*2;
            float bz0 = __ldg(bbp + oc0);
            float bz1 = __ldg(bbp + oc0 + 1);
            p0[(size_t)oc0*HWs]       = acc[mt][nt][0] + bz0;
            p0[(size_t)(oc0+1)*HWs]   = acc[mt][nt][1] + bz1;
            p1[(size_t)oc0*HWs]       = acc[mt][nt][2] + bz0;
            p1[(size_t)(oc0+1)*HWs]   = acc[mt][nt][3] + bz1;
        }
    }
}

// ---------------- launch ----------------
extern "C" void kernel_launch(void* const* d_in, const int* in_sizes, int n_in,
                              void* d_out, int out_size) {
    const float* x     = (const float*)d_in[0];
    const float* off_w = (const float*)d_in[1];
    const float* off_b = (const float*)d_in[2];
    const float* def_w = (const float*)d_in[3];
    const float* def_b = (const float*)d_in[4];
    float* out = (float*)d_out;

    cudaFuncSetAttribute(offset_mma_kernel, cudaFuncAttributeMaxDynamicSharedMemorySize,
                         OSM_TOTAL);                              // 73728 B
    cudaFuncSetAttribute(deform_kernel, cudaFuncAttributeMaxDynamicSharedMemorySize,
                         SM_TOTAL);                               // 81920 B

    prep_kernel<<<(GG*KK*CGc*CGc + 255) / 256, 256>>>(off_w, def_w);
    quad_kernel<<<BB*GG*CGc*HWs/256, 256>>>(x);
    offset_mma_kernel<<<BB*GG*(HH/4), 256, OSM_TOTAL>>>(x, off_b);
    deform_kernel<<<BB*GG*(HH/4), 256, SM_TOTAL>>>(def_b, out);
}

// round 14
// speedup vs baseline: 1.2499x; 1.1455x over previous
#include <cuda_runtime.h>
#include <cuda_bf16.h>
#include <math.h>
#include <stdint.h>

#define BB 16
#define GG 4
#define CGc 64
#define HH 64
#define WW 64
#define HWs 4096
#define KK 9

// ---------------- scratch (static; no allocation) ----------------
__device__ float g_off[BB*GG*18*HWs];                 // offsets [bg][c=2k+j][h][w]
__device__ float4 g_xQ[BB*GG*CGc*HWs];                // corner quads: (v[y][x], v[y][x+1], v[y+1][x], v[y+1][x+1])  (268MB)
__device__ __nv_bfloat16 g_wbh[GG*KK*CGc*CGc];        // def_w bf16 hi, pre-SW128-swizzled rows [oc][ic]
__device__ __nv_bfloat16 g_wbl[GG*KK*CGc*CGc];        // def_w bf16 lo, same layout
__device__ __nv_bfloat16 g_owbh[GG*KK*32*CGc];        // off_w bf16 hi, SW128 rows [oc(32 pad)][ic]
__device__ __nv_bfloat16 g_owbl[GG*KK*32*CGc];        // off_w bf16 lo

#define SWZ128(off) ((off) ^ (((off) >> 3) & 0x70))

// ---------------- helpers ----------------
__device__ __forceinline__ uint32_t smem_u32(const void* p) {
    uint32_t a;
    asm("{ .reg .u64 t; cvta.to.shared.u64 t, %1; cvt.u32.u64 %0, t; }" : "=r"(a) : "l"(p));
    return a;
}
__device__ __forceinline__ void ldsm_x4(uint32_t* r, uint32_t addr) {
    asm volatile("ldmatrix.sync.aligned.m8n8.x4.shared.b16 {%0,%1,%2,%3}, [%4];"
        : "=r"(r[0]), "=r"(r[1]), "=r"(r[2]), "=r"(r[3]) : "r"(addr));
}
__device__ __forceinline__ void mma_bf16(float* d, const uint32_t* a, uint32_t b0, uint32_t b1) {
    asm volatile(
        "mma.sync.aligned.m16n8k16.row.col.f32.bf16.bf16.f32 "
        "{%0,%1,%2,%3}, {%4,%5,%6,%7}, {%8,%9}, {%0,%1,%2,%3};"
        : "+f"(d[0]), "+f"(d[1]), "+f"(d[2]), "+f"(d[3])
        : "r"(a[0]), "r"(a[1]), "r"(a[2]), "r"(a[3]), "r"(b0), "r"(b1));
}

// ---------------- prep: weight transforms ----------------
__global__ void prep_kernel(const float* __restrict__ off_w,
                            const float* __restrict__ def_w) {
    int idx = blockIdx.x * blockDim.x + threadIdx.x;
    const int n_w = GG*KK*CGc*CGc;    // 147456
    if (idx < n_w) {
        int ic = idx & 63;
        int oc = (idx >> 6) & 63;
        int gk = idx >> 12;           // g*9+k
        int k  = gk % KK;
        int g  = gk / KK;
        float w = def_w[((g*CGc + oc)*CGc + ic)*KK + k];
        __nv_bfloat16 hi = __float2bfloat16(w);
        float lo = w - __bfloat162float(hi);
        uint32_t sw = SWZ128((uint32_t)(oc*128 + ic*2));
        size_t base = (size_t)(g*KK + k) * CGc * CGc;
        g_wbh[base + sw/2] = hi;
        g_wbl[base + sw/2] = __float2bfloat16(lo);
    }
    const int n_ow = GG*KK*32*CGc;    // 73728  offset-conv weights, oc padded to 32
    if (idx < n_ow) {
        int ic = idx & 63;
        int oc = (idx >> 6) & 31;
        int gk = idx >> 11;           // g*9+k
        int k  = gk % KK;
        int g  = gk / KK;
        float w = (oc < 18) ? off_w[((g*18 + oc)*CGc + ic)*KK + k] : 0.0f;
        __nv_bfloat16 hi = __float2bfloat16(w);
        float lo = w - __bfloat162float(hi);
        uint32_t sw = SWZ128((uint32_t)(oc*128 + ic*2));
        size_t base = (size_t)(g*KK + k) * 32 * CGc;
        g_owbh[base + sw/2] = hi;
        g_owbl[base + sw/2] = __float2bfloat16(lo);
    }
}

// ---------------- quad build: all 4 bilinear corners in one float4 ----------------
__global__ void __launch_bounds__(256) quad_kernel(const float* __restrict__ x) {
    size_t i = (size_t)blockIdx.x * 256 + threadIdx.x;   // over BB*GG*CGc*HWs
    int xc = (int)(i & 63);
    int yc = (int)((i >> 6) & 63);
    float v00 = x[i];
    float v01 = (xc < 63) ? x[i + 1]  : v00;
    float v10 = (yc < 63) ? x[i + 64] : v00;
    float v11 = (yc < 63) ? ((xc < 63) ? x[i + 65] : v10) : v01;
    g_xQ[i] = make_float4(v00, v01, v10, v11);
}

// ---------------- offset conv via mma.sync: 64 -> 18(pad 32), 3x3 (UNCHANGED R10) ----------------
#define OSM_SHI  0
#define OSM_SLO  32768
#define OSM_WHI  65536
#define OSM_WLO  69632
#define OSM_TOTAL 73728

extern __shared__ char osmem[];
__global__ void __launch_bounds__(256) offset_mma_kernel(const float* __restrict__ x,
                                                         const float* __restrict__ off_b) {
    char* sm = osmem;
    uint32_t smem_base = smem_u32(sm);
    int tid  = threadIdx.x;
    int wid  = tid >> 5;
    int lane = tid & 31;

    int bid  = blockIdx.x;
    int hblk = bid & 15;
    int g    = (bid >> 4) & 3;
    int b    = bid >> 6;
    int bg   = b*GG + g;

    int m    = tid;
    int r    = m >> 6;
    int wpos = m & 63;
    int h    = hblk*4 + r;

    const float* xb = x + (size_t)bg * CGc * HWs;

    char* shi_row = sm + OSM_SHI + m*128;
    char* slo_row = sm + OSM_SLO + m*128;
    uint32_t swz = (uint32_t)((m & 7) << 4);

    float acc[2][4][4];
#pragma unroll
    for (int mt = 0; mt < 2; mt++)
#pragma unroll
        for (int nt = 0; nt < 4; nt++)
#pragma unroll
            for (int q = 0; q < 4; q++) acc[mt][nt][q] = 0.0f;

    int a_row0   = wid*32 + (lane & 15);
    int ab_colsl = (lane >> 4) << 4;
    int b_row0   = ((lane >> 3) & 1)*8 + (lane & 7);

    for (int k = 0; k < KK; k++) {
        {
            const uint4* s1 = (const uint4*)(g_owbh + (size_t)(g*KK + k) * 32 * CGc);
            const uint4* s2 = (const uint4*)(g_owbl + (size_t)(g*KK + k) * 32 * CGc);
            ((uint4*)(sm + OSM_WHI))[tid] = s1[tid];
            ((uint4*)(sm + OSM_WLO))[tid] = s2[tid];
        }

        int dy = k/3 - 1, dx = k%3 - 1;
        int y    = h + dy;
        int xcol = wpos + dx;
        bool valid = (y >= 0 && y < HH && xcol >= 0 && xcol < WW);
        const float* xs = xb + y*WW + xcol;
#pragma unroll
        for (int icp = 0; icp < 8; icp++) {
            uint32_t hp[4], lp[4];
#pragma unroll
            for (int jj = 0; jj < 2; jj++) {
                int ic = icp*8 + jj*4;
                float v0 = valid ? __ldg(xs + (size_t)(ic  )*HWs) : 0.0f;
                float v1 = valid ? __ldg(xs + (size_t)(ic+1)*HWs) : 0.0f;
                float v2 = valid ? __ldg(xs + (size_t)(ic+2)*HWs) : 0.0f;
                float v3 = valid ? __ldg(xs + (size_t)(ic+3)*HWs) : 0.0f;
                uint32_t hh0, hh1;
                asm("cvt.rn.bf16x2.f32 %0, %1, %2;" : "=r"(hh0) : "f"(v1), "f"(v0));
                asm("cvt.rn.bf16x2.f32 %0, %1, %2;" : "=r"(hh1) : "f"(v3), "f"(v2));
                float l0 = v0 - __uint_as_float(hh0 << 16);
                float l1 = v1 - __uint_as_float(hh0 & 0xffff0000u);
                float l2 = v2 - __uint_as_float(hh1 << 16);
                float l3 = v3 - __uint_as_float(hh1 & 0xffff0000u);
                uint32_t ll0, ll1;
                asm("cvt.rn.bf16x2.f32 %0, %1, %2;" : "=r"(ll0) : "f"(l1), "f"(l0));
                asm("cvt.rn.bf16x2.f32 %0, %1, %2;" : "=r"(ll1) : "f"(l3), "f"(l2));
                hp[2*jj] = hh0; hp[2*jj+1] = hh1;
                lp[2*jj] = ll0; lp[2*jj+1] = ll1;
            }
            uint32_t off = ((uint32_t)(icp*16)) ^ swz;
            *(uint4*)(shi_row + off) = make_uint4(hp[0], hp[1], hp[2], hp[3]);
            *(uint4*)(slo_row + off) = make_uint4(lp[0], lp[1], lp[2], lp[3]);
        }
        __syncthreads();

#pragma unroll
        for (int kc = 0; kc < 4; kc++) {
            int colb = kc*32 + ab_colsl;
            uint32_t ah[2][4], al[2][4];
#pragma unroll
            for (int mt = 0; mt < 2; mt++) {
                int row = a_row0 + mt*16;
                uint32_t boff = (uint32_t)(row*128 + (colb ^ ((row & 7) << 4)));
                ldsm_x4(ah[mt], smem_base + OSM_SHI + boff);
                ldsm_x4(al[mt], smem_base + OSM_SLO + boff);
            }
#pragma unroll
            for (int ntp = 0; ntp < 2; ntp++) {
                int nrow = b_row0 + ntp*16;
                uint32_t boff = (uint32_t)(nrow*128 + (colb ^ ((nrow & 7) << 4)));
                uint32_t bh[4], bl[4];
                ldsm_x4(bh, smem_base + OSM_WHI + boff);
                ldsm_x4(bl, smem_base + OSM_WLO + boff);
#pragma unroll
                for (int mt = 0; mt < 2; mt++) {
                    mma_bf16(acc[mt][2*ntp  ], ah[mt], bh[0], bh[2]);
                    mma_bf16(acc[mt][2*ntp  ], ah[mt], bl[0], bl[2]);
                    mma_bf16(acc[mt][2*ntp  ], al[mt], bh[0], bh[2]);
                    mma_bf16(acc[mt][2*ntp+1], ah[mt], bh[1], bh[3]);
                    mma_bf16(acc[mt][2*ntp+1], ah[mt], bl[1], bl[3]);
                    mma_bf16(acc[mt][2*ntp+1], al[mt], bh[1], bh[3]);
                }
            }
        }
        __syncthreads();
    }

    float* og = g_off + (size_t)bg * 18 * HWs + hblk*4*64;
    const float* obp = off_b + g*18;
#pragma unroll
    for (int mt = 0; mt < 2; mt++) {
        int row0  = wid*32 + mt*16 + (lane >> 2);
        int h_loc = row0 >> 6;
        int wp    = row0 & 63;
        float* p0 = og + h_loc*64 + wp;
        float* p1 = p0 + 8;
#pragma unroll
        for (int nt = 0; nt < 4; nt++) {
            int c0 = nt*8 + (lane & 3)*2;
            if (c0 < 18) {
                float bz0 = __ldg(obp + c0);
                float bz1 = __ldg(obp + c0 + 1);
                p0[(size_t)c0*HWs]     = acc[mt][nt][0] + bz0;
                p0[(size_t)(c0+1)*HWs] = acc[mt][nt][1] + bz1;
                p1[(size_t)c0*HWs]     = acc[mt][nt][2] + bz0;
                p1[(size_t)(c0+1)*HWs] = acc[mt][nt][3] + bz1;
            }
        }
    }
}

// ---------------- deformable conv: mma.sync bf16x2 GEMM (quad gather, 2 blocks/SM forced) ----------------
// block = (b, g, hblk of 4 rows); 256 threads (8 warps)
// M=256 (4h x 64w), N=64 oc, K per tap = 64 ic, 9 taps
#define SM_SHI  0        // S hi [256 x 64] bf16 SW128 : 32768 B
#define SM_SLO  32768    // S lo                       : 32768 B
#define SM_WHI  65536    // W hi [64 x 64] bf16 SW128  :  8192 B
#define SM_WLO  73728    // W lo                       :  8192 B
#define SM_TOTAL 81920

extern __shared__ char smem2[];
__global__ void __launch_bounds__(256, 2) deform_kernel(const float* __restrict__ def_b,
                                                        float* __restrict__ out) {
    char* sm = smem2;
    uint32_t smem_base = smem_u32(sm);
    int tid  = threadIdx.x;
    int wid  = tid >> 5;
    int lane = tid & 31;

    int bid  = blockIdx.x;
    int hblk = bid & 15;
    int g    = (bid >> 4) & 3;
    int b    = bid >> 6;
    int bg   = b*GG + g;

    int m    = tid;            // S-tile row this thread gathers
    int r    = m >> 6;         // 0..3
    int wpos = m & 63;
    int h    = hblk*4 + r;

    const float4* xQb = g_xQ + (size_t)bg * CGc * HWs;
    const float* offp = g_off + (size_t)bg * 18 * HWs + h*64 + wpos;

    char* shi_row = sm + SM_SHI + m*128;
    char* slo_row = sm + SM_SLO + m*128;
    uint32_t swz = (uint32_t)((m & 7) << 4);

    float acc[2][8][4];
#pragma unroll
    for (int mt = 0; mt < 2; mt++)
#pragma unroll
        for (int nt = 0; nt < 8; nt++)
#pragma unroll
            for (int q = 0; q < 4; q++) acc[mt][nt][q] = 0.0f;

    int a_row0   = wid*32 + (lane & 15);
    int ab_colsl = (lane >> 4) << 4;
    int b_row0   = ((lane >> 3) & 1)*8 + (lane & 7);

    for (int k = 0; k < KK; k++) {
        // ---- fill W tiles (pre-swizzled gmem -> linear copy) ----
        {
            const uint4* s1 = (const uint4*)(g_wbh + (size_t)(g*KK + k) * CGc * CGc);
            const uint4* s2 = (const uint4*)(g_wbl + (size_t)(g*KK + k) * CGc * CGc);
            uint4* d1 = (uint4*)(sm + SM_WHI);
            uint4* d2 = (uint4*)(sm + SM_WLO);
#pragma unroll
            for (int i = 0; i < 2; i++) {
                d1[tid + i*256] = s1[tid + i*256];
                d2[tid + i*256] = s2[tid + i*256];
            }
        }

        // ---- per-thread bilinear corner precompute ----
        float dy = __ldg(offp + (2*k    )*HWs);
        float dx = __ldg(offp + (2*k + 1)*HWs);
        float py = dy + (float)(k/3 - 1) + (float)h;
        float px = dx + (float)(k%3 - 1) + (float)wpos;
        float fy = floorf(py), fx = floorf(px);
        float wy = py - fy,    wx = px - fx;
        int y0 = (int)fy, x0 = (int)fx;
        int y1 = y0 + 1,  x1 = x0 + 1;
        float vy0 = (y0 >= 0 && y0 < HH) ? 1.f : 0.f;
        float vy1 = (y1 >= 0 && y1 < HH) ? 1.f : 0.f;
        float vx0 = (x0 >= 0 && x0 < WW) ? 1.f : 0.f;
        float vx1 = (x1 >= 0 && x1 < WW) ? 1.f : 0.f;
        float c00 = (1.f-wy)*(1.f-wx) * vy0 * vx0;
        float c01 = (1.f-wy)*wx       * vy0 * vx1;
        float c10 = wy*(1.f-wx)       * vy1 * vx0;
        float c11 = wy*wx             * vy1 * vx1;
        // quad slot fixups (battle-tested in R9/R12 forms)
        if (x0 < 0) { c00 = c01; c01 = 0.f; c10 = c11; c11 = 0.f; }
        if (y0 < 0) { c00 = c10; c01 = c11; c10 = 0.f; c11 = 0.f; }
        int xl = min(max(x0,0),WW-1);
        int yb = min(max(y0,0),HH-1);
        int o  = yb*WW + xl;

        // ---- gather (quad LDG.128) + bf16 hi/lo split into S tiles ----
#pragma unroll
        for (int icp = 0; icp < 8; icp++) {
            uint32_t hp[4], lp[4];
#pragma unroll
            for (int jj = 0; jj < 2; jj++) {
                int ic = icp*8 + jj*4;
                float4 q0 = __ldg(xQb + (size_t)ic*HWs + o);
                float4 q1 = __ldg(xQb + (size_t)(ic+1)*HWs + o);
                float4 q2 = __ldg(xQb + (size_t)(ic+2)*HWs + o);
                float4 q3 = __ldg(xQb + (size_t)(ic+3)*HWs + o);
                float v0 = c00*q0.x + c01*q0.y + c10*q0.z + c11*q0.w;
                float v1 = c00*q1.x + c01*q1.y + c10*q1.z + c11*q1.w;
                float v2 = c00*q2.x + c01*q2.y + c10*q2.z + c11*q2.w;
                float v3 = c00*q3.x + c01*q3.y + c10*q3.z + c11*q3.w;
                uint32_t hh0, hh1;
                asm("cvt.rn.bf16x2.f32 %0, %1, %2;" : "=r"(hh0) : "f"(v1), "f"(v0));
                asm("cvt.rn.bf16x2.f32 %0, %1, %2;" : "=r"(hh1) : "f"(v3), "f"(v2));
                float l0 = v0 - __uint_as_float(hh0 << 16);
                float l1 = v1 - __uint_as_float(hh0 & 0xffff0000u);
                float l2 = v2 - __uint_as_float(hh1 << 16);
                float l3 = v3 - __uint_as_float(hh1 & 0xffff0000u);
                uint32_t ll0, ll1;
                asm("cvt.rn.bf16x2.f32 %0, %1, %2;" : "=r"(ll0) : "f"(l1), "f"(l0));
                asm("cvt.rn.bf16x2.f32 %0, %1, %2;" : "=r"(ll1) : "f"(l3), "f"(l2));
                hp[2*jj] = hh0; hp[2*jj+1] = hh1;
                lp[2*jj] = ll0; lp[2*jj+1] = ll1;
            }
            uint32_t off = ((uint32_t)(icp*16)) ^ swz;
            *(uint4*)(shi_row + off) = make_uint4(hp[0], hp[1], hp[2], hp[3]);
            *(uint4*)(slo_row + off) = make_uint4(lp[0], lp[1], lp[2], lp[3]);
        }
        __syncthreads();

        // ---- MMA: 4 k16-chunks x (2 m-tiles x 8 n-tiles) x 3 bf16x2 terms ----
#pragma unroll
        for (int kc = 0; kc < 4; kc++) {
            int colb = kc*32 + ab_colsl;
            uint32_t ah[2][4], al[2][4];
#pragma unroll
            for (int mt = 0; mt < 2; mt++) {
                int row = a_row0 + mt*16;
                uint32_t boff = (uint32_t)(row*128 + (colb ^ ((row & 7) << 4)));
                ldsm_x4(ah[mt], smem_base + SM_SHI + boff);
                ldsm_x4(al[mt], smem_base + SM_SLO + boff);
            }
#pragma unroll
            for (int ntp = 0; ntp < 4; ntp++) {
                int nrow = b_row0 + ntp*16;
                uint32_t boff = (uint32_t)(nrow*128 + (colb ^ ((nrow & 7) << 4)));
                uint32_t bh[4], bl[4];
                ldsm_x4(bh, smem_base + SM_WHI + boff);
                ldsm_x4(bl, smem_base + SM_WLO + boff);
#pragma unroll
                for (int mt = 0; mt < 2; mt++) {
                    mma_bf16(acc[mt][2*ntp  ], ah[mt], bh[0], bh[2]);
                    mma_bf16(acc[mt][2*ntp  ], ah[mt], bl[0], bl[2]);
                    mma_bf16(acc[mt][2*ntp  ], al[mt], bh[0], bh[2]);
                    mma_bf16(acc[mt][2*ntp+1], ah[mt], bh[1], bh[3]);
                    mma_bf16(acc[mt][2*ntp+1], ah[mt], bl[1], bl[3]);
                    mma_bf16(acc[mt][2*ntp+1], al[mt], bh[1], bh[3]);
                }
            }
        }
        __syncthreads();
    }

    // ---- epilogue: fragment scatter to gmem (+bias) ----
    float* outg = out + (size_t)bg * CGc * HWs + hblk*4*64;
    const float* bbp = def_b + g*CGc;
#pragma unroll
    for (int mt = 0; mt < 2; mt++) {
        int row0  = wid*32 + mt*16 + (lane >> 2);
        int h_loc = row0 >> 6;
        int wp    = row0 & 63;
        float* p0 = outg + h_loc*64 + wp;
        float* p1 = p0 + 8;
#pragma unroll
        for (int nt = 0; nt < 8; nt++) {
            int oc0 = nt*8 + (lane & 3)*2;
            float bz0 = __ldg(bbp + oc0);
            float bz1 = __ldg(bbp + oc0 + 1);
            p0[(size_t)oc0*HWs]       = acc[mt][nt][0] + bz0;
            p0[(size_t)(oc0+1)*HWs]   = acc[mt][nt][1] + bz1;
            p1[(size_t)oc0*HWs]       = acc[mt][nt][2] + bz0;
            p1[(size_t)(oc0+1)*HWs]   = acc[mt][nt][3] + bz1;
        }
    }
}

// ---------------- launch ----------------
extern "C" void kernel_launch(void* const* d_in, const int* in_sizes, int n_in,
                              void* d_out, int out_size) {
    const float* x     = (const float*)d_in[0];
    const float* off_w = (const float*)d_in[1];
    const float* off_b = (const float*)d_in[2];
    const float* def_w = (const float*)d_in[3];
    const float* def_b = (const float*)d_in[4];
    float* out = (float*)d_out;

    cudaFuncSetAttribute(offset_mma_kernel, cudaFuncAttributeMaxDynamicSharedMemorySize,
                         OSM_TOTAL);                              // 73728 B
    cudaFuncSetAttribute(deform_kernel, cudaFuncAttributeMaxDynamicSharedMemorySize,
                         SM_TOTAL);                               // 81920 B

    prep_kernel<<<(GG*KK*CGc*CGc + 255) / 256, 256>>>(off_w, def_w);
    quad_kernel<<<BB*GG*CGc*HWs/256, 256>>>(x);
    offset_mma_kernel<<<BB*GG*(HH/4), 256, OSM_TOTAL>>>(x, off_b);
    deform_kernel<<<BB*GG*(HH/4), 256, SM_TOTAL>>>(def_b, out);
}

// round 16
// speedup vs baseline: 1.2509x; 1.0009x over previous
#include <cuda_runtime.h>
#include <cuda_bf16.h>
#include <cuda_fp16.h>
#include <math.h>
#include <stdint.h>

#define BB 16
#define GG 4
#define CGc 64
#define HH 64
#define WW 64
#define HWs 4096
#define KK 9

// ---------------- scratch (static; no allocation) ----------------
__device__ float g_off[BB*GG*18*HWs];                 // offsets [bg][c=2k+j][h][w]
__device__ float4 g_xQ[BB*GG*CGc*HWs];                // corner quads (268MB)
__device__ __nv_half g_wfh[GG*KK*CGc*CGc];            // def_w fp16, pre-SW128-swizzled rows [oc][ic]
__device__ __nv_bfloat16 g_owbh[GG*KK*32*CGc];        // off_w bf16 hi, SW128 rows [oc(32 pad)][ic]
__device__ __nv_bfloat16 g_owbl[GG*KK*32*CGc];        // off_w bf16 lo

#define SWZ128(off) ((off) ^ (((off) >> 3) & 0x70))

// ---------------- helpers ----------------
__device__ __forceinline__ uint32_t smem_u32(const void* p) {
    uint32_t a;
    asm("{ .reg .u64 t; cvta.to.shared.u64 t, %1; cvt.u32.u64 %0, t; }" : "=r"(a) : "l"(p));
    return a;
}
__device__ __forceinline__ void ldsm_x4(uint32_t* r, uint32_t addr) {
    asm volatile("ldmatrix.sync.aligned.m8n8.x4.shared.b16 {%0,%1,%2,%3}, [%4];"
        : "=r"(r[0]), "=r"(r[1]), "=r"(r[2]), "=r"(r[3]) : "r"(addr));
}
__device__ __forceinline__ void mma_bf16(float* d, const uint32_t* a, uint32_t b0, uint32_t b1) {
    asm volatile(
        "mma.sync.aligned.m16n8k16.row.col.f32.bf16.bf16.f32 "
        "{%0,%1,%2,%3}, {%4,%5,%6,%7}, {%8,%9}, {%0,%1,%2,%3};"
        : "+f"(d[0]), "+f"(d[1]), "+f"(d[2]), "+f"(d[3])
        : "r"(a[0]), "r"(a[1]), "r"(a[2]), "r"(a[3]), "r"(b0), "r"(b1));
}
__device__ __forceinline__ void mma_f16(float* d, const uint32_t* a, uint32_t b0, uint32_t b1) {
    asm volatile(
        "mma.sync.aligned.m16n8k16.row.col.f32.f16.f16.f32 "
        "{%0,%1,%2,%3}, {%4,%5,%6,%7}, {%8,%9}, {%0,%1,%2,%3};"
        : "+f"(d[0]), "+f"(d[1]), "+f"(d[2]), "+f"(d[3])
        : "r"(a[0]), "r"(a[1]), "r"(a[2]), "r"(a[3]), "r"(b0), "r"(b1));
}

// ---------------- prep: weight transforms ----------------
__global__ void prep_kernel(const float* __restrict__ off_w,
                            const float* __restrict__ def_w) {
    int idx = blockIdx.x * blockDim.x + threadIdx.x;
    const int n_w = GG*KK*CGc*CGc;    // 147456
    if (idx < n_w) {
        int ic = idx & 63;
        int oc = (idx >> 6) & 63;
        int gk = idx >> 12;           // g*9+k
        int k  = gk % KK;
        int g  = gk / KK;
        float w = def_w[((g*CGc + oc)*CGc + ic)*KK + k];
        uint32_t sw = SWZ128((uint32_t)(oc*128 + ic*2));
        size_t base = (size_t)(g*KK + k) * CGc * CGc;
        g_wfh[base + sw/2] = __float2half(w);
    }
    const int n_ow = GG*KK*32*CGc;    // 73728  offset-conv weights, oc padded to 32
    if (idx < n_ow) {
        int ic = idx & 63;
        int oc = (idx >> 6) & 31;
        int gk = idx >> 11;           // g*9+k
        int k  = gk % KK;
        int g  = gk / KK;
        float w = (oc < 18) ? off_w[((g*18 + oc)*CGc + ic)*KK + k] : 0.0f;
        __nv_bfloat16 hi = __float2bfloat16(w);
        float lo = w - __bfloat162float(hi);
        uint32_t sw = SWZ128((uint32_t)(oc*128 + ic*2));
        size_t base = (size_t)(g*KK + k) * 32 * CGc;
        g_owbh[base + sw/2] = hi;
        g_owbl[base + sw/2] = __float2bfloat16(lo);
    }
}

// ---------------- quad build: all 4 bilinear corners in one float4 ----------------
__global__ void __launch_bounds__(256) quad_kernel(const float* __restrict__ x) {
    size_t i = (size_t)blockIdx.x * 256 + threadIdx.x;   // over BB*GG*CGc*HWs
    int xc = (int)(i & 63);
    int yc = (int)((i >> 6) & 63);
    float v00 = x[i];
    float v01 = (xc < 63) ? x[i + 1]  : v00;
    float v10 = (yc < 63) ? x[i + 64] : v00;
    float v11 = (yc < 63) ? ((xc < 63) ? x[i + 65] : v10) : v01;
    g_xQ[i] = make_float4(v00, v01, v10, v11);
}

// ---------------- offset conv via mma.sync: 64 -> 18(pad 32), 3x3 (UNCHANGED bf16 3-term) ----------------
#define OSM_SHI  0
#define OSM_SLO  32768
#define OSM_WHI  65536
#define OSM_WLO  69632
#define OSM_TOTAL 73728

extern __shared__ char osmem[];
__global__ void __launch_bounds__(256) offset_mma_kernel(const float* __restrict__ x,
                                                         const float* __restrict__ off_b) {
    char* sm = osmem;
    uint32_t smem_base = smem_u32(sm);
    int tid  = threadIdx.x;
    int wid  = tid >> 5;
    int lane = tid & 31;

    int bid  = blockIdx.x;
    int hblk = bid & 15;
    int g    = (bid >> 4) & 3;
    int b    = bid >> 6;
    int bg   = b*GG + g;

    int m    = tid;
    int r    = m >> 6;
    int wpos = m & 63;
    int h    = hblk*4 + r;

    const float* xb = x + (size_t)bg * CGc * HWs;

    char* shi_row = sm + OSM_SHI + m*128;
    char* slo_row = sm + OSM_SLO + m*128;
    uint32_t swz = (uint32_t)((m & 7) << 4);

    float acc[2][4][4];
#pragma unroll
    for (int mt = 0; mt < 2; mt++)
#pragma unroll
        for (int nt = 0; nt < 4; nt++)
#pragma unroll
            for (int q = 0; q < 4; q++) acc[mt][nt][q] = 0.0f;

    int a_row0   = wid*32 + (lane & 15);
    int ab_colsl = (lane >> 4) << 4;
    int b_row0   = ((lane >> 3) & 1)*8 + (lane & 7);

    for (int k = 0; k < KK; k++) {
        {
            const uint4* s1 = (const uint4*)(g_owbh + (size_t)(g*KK + k) * 32 * CGc);
            const uint4* s2 = (const uint4*)(g_owbl + (size_t)(g*KK + k) * 32 * CGc);
            ((uint4*)(sm + OSM_WHI))[tid] = s1[tid];
            ((uint4*)(sm + OSM_WLO))[tid] = s2[tid];
        }

        int dy = k/3 - 1, dx = k%3 - 1;
        int y    = h + dy;
        int xcol = wpos + dx;
        bool valid = (y >= 0 && y < HH && xcol >= 0 && xcol < WW);
        const float* xs = xb + y*WW + xcol;
#pragma unroll
        for (int icp = 0; icp < 8; icp++) {
            uint32_t hp[4], lp[4];
#pragma unroll
            for (int jj = 0; jj < 2; jj++) {
                int ic = icp*8 + jj*4;
                float v0 = valid ? __ldg(xs + (size_t)(ic  )*HWs) : 0.0f;
                float v1 = valid ? __ldg(xs + (size_t)(ic+1)*HWs) : 0.0f;
                float v2 = valid ? __ldg(xs + (size_t)(ic+2)*HWs) : 0.0f;
                float v3 = valid ? __ldg(xs + (size_t)(ic+3)*HWs) : 0.0f;
                uint32_t hh0, hh1;
                asm("cvt.rn.bf16x2.f32 %0, %1, %2;" : "=r"(hh0) : "f"(v1), "f"(v0));
                asm("cvt.rn.bf16x2.f32 %0, %1, %2;" : "=r"(hh1) : "f"(v3), "f"(v2));
                float l0 = v0 - __uint_as_float(hh0 << 16);
                float l1 = v1 - __uint_as_float(hh0 & 0xffff0000u);
                float l2 = v2 - __uint_as_float(hh1 << 16);
                float l3 = v3 - __uint_as_float(hh1 & 0xffff0000u);
                uint32_t ll0, ll1;
                asm("cvt.rn.bf16x2.f32 %0, %1, %2;" : "=r"(ll0) : "f"(l1), "f"(l0));
                asm("cvt.rn.bf16x2.f32 %0, %1, %2;" : "=r"(ll1) : "f"(l3), "f"(l2));
                hp[2*jj] = hh0; hp[2*jj+1] = hh1;
                lp[2*jj] = ll0; lp[2*jj+1] = ll1;
            }
            uint32_t off = ((uint32_t)(icp*16)) ^ swz;
            *(uint4*)(shi_row + off) = make_uint4(hp[0], hp[1], hp[2], hp[3]);
            *(uint4*)(slo_row + off) = make_uint4(lp[0], lp[1], lp[2], lp[3]);
        }
        __syncthreads();

#pragma unroll
        for (int kc = 0; kc < 4; kc++) {
            int colb = kc*32 + ab_colsl;
            uint32_t ah[2][4], al[2][4];
#pragma unroll
            for (int mt = 0; mt < 2; mt++) {
                int row = a_row0 + mt*16;
                uint32_t boff = (uint32_t)(row*128 + (colb ^ ((row & 7) << 4)));
                ldsm_x4(ah[mt], smem_base + OSM_SHI + boff);
                ldsm_x4(al[mt], smem_base + OSM_SLO + boff);
            }
#pragma unroll
            for (int ntp = 0; ntp < 2; ntp++) {
                int nrow = b_row0 + ntp*16;
                uint32_t boff = (uint32_t)(nrow*128 + (colb ^ ((nrow & 7) << 4)));
                uint32_t bh[4], bl[4];
                ldsm_x4(bh, smem_base + OSM_WHI + boff);
                ldsm_x4(bl, smem_base + OSM_WLO + boff);
#pragma unroll
                for (int mt = 0; mt < 2; mt++) {
                    mma_bf16(acc[mt][2*ntp  ], ah[mt], bh[0], bh[2]);
                    mma_bf16(acc[mt][2*ntp  ], ah[mt], bl[0], bl[2]);
                    mma_bf16(acc[mt][2*ntp  ], al[mt], bh[0], bh[2]);
                    mma_bf16(acc[mt][2*ntp+1], ah[mt], bh[1], bh[3]);
                    mma_bf16(acc[mt][2*ntp+1], ah[mt], bl[1], bl[3]);
                    mma_bf16(acc[mt][2*ntp+1], al[mt], bh[1], bh[3]);
                }
            }
        }
        __syncthreads();
    }

    float* og = g_off + (size_t)bg * 18 * HWs + hblk*4*64;
    const float* obp = off_b + g*18;
#pragma unroll
    for (int mt = 0; mt < 2; mt++) {
        int row0  = wid*32 + mt*16 + (lane >> 2);
        int h_loc = row0 >> 6;
        int wp    = row0 & 63;
        float* p0 = og + h_loc*64 + wp;
        float* p1 = p0 + 8;
#pragma unroll
        for (int nt = 0; nt < 4; nt++) {
            int c0 = nt*8 + (lane & 3)*2;
            if (c0 < 18) {
                float bz0 = __ldg(obp + c0);
                float bz1 = __ldg(obp + c0 + 1);
                p0[(size_t)c0*HWs]     = acc[mt][nt][0] + bz0;
                p0[(size_t)(c0+1)*HWs] = acc[mt][nt][1] + bz1;
                p1[(size_t)c0*HWs]     = acc[mt][nt][2] + bz0;
                p1[(size_t)(c0+1)*HWs] = acc[mt][nt][3] + bz1;
            }
        }
    }
}

// ---------------- deformable conv: mma.sync fp16 single-term GEMM ----------------
// block = (b, g, hblk of 4 rows); 256 threads (8 warps), 2 blocks/SM
// M=256 (4h x 64w), N=64 oc, K per tap = 64 ic, 9 taps
#define SM_SH  0         // S fp16 [256 x 64] SW128 : 32768 B
#define SM_WH  32768     // W fp16 [64 x 64]  SW128 :  8192 B
#define SM_TOTAL 40960

extern __shared__ char smem2[];
__global__ void __launch_bounds__(256, 2) deform_kernel(const float* __restrict__ def_b,
                                                        float* __restrict__ out) {
    char* sm = smem2;
    uint32_t smem_base = smem_u32(sm);
    int tid  = threadIdx.x;
    int wid  = tid >> 5;
    int lane = tid & 31;

    int bid  = blockIdx.x;
    int hblk = bid & 15;
    int g    = (bid >> 4) & 3;
    int b    = bid >> 6;
    int bg   = b*GG + g;

    int m    = tid;            // S-tile row this thread gathers
    int r    = m >> 6;         // 0..3
    int wpos = m & 63;
    int h    = hblk*4 + r;

    const float4* xQb = g_xQ + (size_t)bg * CGc * HWs;
    const float* offp = g_off + (size_t)bg * 18 * HWs + h*64 + wpos;

    char* s_row = sm + SM_SH + m*128;
    uint32_t swz = (uint32_t)((m & 7) << 4);

    float acc[2][8][4];
#pragma unroll
    for (int mt = 0; mt < 2; mt++)
#pragma unroll
        for (int nt = 0; nt < 8; nt++)
#pragma unroll
            for (int q = 0; q < 4; q++) acc[mt][nt][q] = 0.0f;

    int a_row0   = wid*32 + (lane & 15);
    int ab_colsl = (lane >> 4) << 4;
    int b_row0   = ((lane >> 3) & 1)*8 + (lane & 7);

    for (int k = 0; k < KK; k++) {
        // ---- fill W tile (pre-swizzled gmem -> linear copy, 8KB) ----
        {
            const uint4* s1 = (const uint4*)(g_wfh + (size_t)(g*KK + k) * CGc * CGc);
            uint4* d1 = (uint4*)(sm + SM_WH);
#pragma unroll
            for (int i = 0; i < 2; i++) d1[tid + i*256] = s1[tid + i*256];
        }

        // ---- per-thread bilinear corner precompute ----
        float dy = __ldg(offp + (2*k    )*HWs);
        float dx = __ldg(offp + (2*k + 1)*HWs);
        float py = dy + (float)(k/3 - 1) + (float)h;
        float px = dx + (float)(k%3 - 1) + (float)wpos;
        float fy = floorf(py), fx = floorf(px);
        float wy = py - fy,    wx = px - fx;
        int y0 = (int)fy, x0 = (int)fx;
        int y1 = y0 + 1,  x1 = x0 + 1;
        float vy0 = (y0 >= 0 && y0 < HH) ? 1.f : 0.f;
        float vy1 = (y1 >= 0 && y1 < HH) ? 1.f : 0.f;
        float vx0 = (x0 >= 0 && x0 < WW) ? 1.f : 0.f;
        float vx1 = (x1 >= 0 && x1 < WW) ? 1.f : 0.f;
        float c00 = (1.f-wy)*(1.f-wx) * vy0 * vx0;
        float c01 = (1.f-wy)*wx       * vy0 * vx1;
        float c10 = wy*(1.f-wx)       * vy1 * vx0;
        float c11 = wy*wx             * vy1 * vx1;
        // quad slot fixups (battle-tested)
        if (x0 < 0) { c00 = c01; c01 = 0.f; c10 = c11; c11 = 0.f; }
        if (y0 < 0) { c00 = c10; c01 = c11; c10 = 0.f; c11 = 0.f; }
        int xl = min(max(x0,0),WW-1);
        int yb = min(max(y0,0),HH-1);
        int o  = yb*WW + xl;

        // ---- gather (quad LDG.128) + fp16 convert into S tile ----
#pragma unroll
        for (int icp = 0; icp < 8; icp++) {
            uint32_t hp[4];
#pragma unroll
            for (int jj = 0; jj < 2; jj++) {
                int ic = icp*8 + jj*4;
                float4 q0 = __ldg(xQb + (size_t)ic*HWs + o);
                float4 q1 = __ldg(xQb + (size_t)(ic+1)*HWs + o);
                float4 q2 = __ldg(xQb + (size_t)(ic+2)*HWs + o);
                float4 q3 = __ldg(xQb + (size_t)(ic+3)*HWs + o);
                float v0 = c00*q0.x + c01*q0.y + c10*q0.z + c11*q0.w;
                float v1 = c00*q1.x + c01*q1.y + c10*q1.z + c11*q1.w;
                float v2 = c00*q2.x + c01*q2.y + c10*q2.z + c11*q2.w;
                float v3 = c00*q3.x + c01*q3.y + c10*q3.z + c11*q3.w;
                uint32_t hh0, hh1;
                asm("cvt.rn.f16x2.f32 %0, %1, %2;" : "=r"(hh0) : "f"(v1), "f"(v0));
                asm("cvt.rn.f16x2.f32 %0, %1, %2;" : "=r"(hh1) : "f"(v3), "f"(v2));
                hp[2*jj] = hh0; hp[2*jj+1] = hh1;
            }
            uint32_t off = ((uint32_t)(icp*16)) ^ swz;
            *(uint4*)(s_row + off) = make_uint4(hp[0], hp[1], hp[2], hp[3]);
        }
        __syncthreads();

        // ---- MMA: 4 k16-chunks x (2 m-tiles x 8 n-tiles), single fp16 term ----
#pragma unroll
        for (int kc = 0; kc < 4; kc++) {
            int colb = kc*32 + ab_colsl;
            uint32_t ah[2][4];
#pragma unroll
            for (int mt = 0; mt < 2; mt++) {
                int row = a_row0 + mt*16;
                uint32_t boff = (uint32_t)(row*128 + (colb ^ ((row & 7) << 4)));
                ldsm_x4(ah[mt], smem_base + SM_SH + boff);
            }
#pragma unroll
            for (int ntp = 0; ntp < 4; ntp++) {
                int nrow = b_row0 + ntp*16;
                uint32_t boff = (uint32_t)(nrow*128 + (colb ^ ((nrow & 7) << 4)));
                uint32_t bh[4];
                ldsm_x4(bh, smem_base + SM_WH + boff);
#pragma unroll
                for (int mt = 0; mt < 2; mt++) {
                    mma_f16(acc[mt][2*ntp  ], ah[mt], bh[0], bh[2]);
                    mma_f16(acc[mt][2*ntp+1], ah[mt], bh[1], bh[3]);
                }
            }
        }
        __syncthreads();
    }

    // ---- epilogue: fragment scatter to gmem (+bias) ----
    float* outg = out + (size_t)bg * CGc * HWs + hblk*4*64;
    const float* bbp = def_b + g*CGc;
#pragma unroll
    for (int mt = 0; mt < 2; mt++) {
        int row0  = wid*32 + mt*16 + (lane >> 2);
        int h_loc = row0 >> 6;
        int wp    = row0 & 63;
        float* p0 = outg + h_loc*64 + wp;
        float* p1 = p0 + 8;
#pragma unroll
        for (int nt = 0; nt < 8; nt++) {
            int oc0 = nt*8 + (lane & 3)*2;
            float bz0 = __ldg(bbp + oc0);
            float bz1 = __ldg(bbp + oc0 + 1);
            p0[(size_t)oc0*HWs]       = acc[mt][nt][0] + bz0;
            p0[(size_t)(oc0+1)*HWs]   = acc[mt][nt][1] + bz1;
            p1[(size_t)oc0*HWs]       = acc[mt][nt][2] + bz0;
            p1[(size_t)(oc0+1)*HWs]   = acc[mt][nt][3] + bz1;
        }
    }
}

// ---------------- launch ----------------
extern "C" void kernel_launch(void* const* d_in, const int* in_sizes, int n_in,
                              void* d_out, int out_size) {
    const float* x     = (const float*)d_in[0];
    const float* off_w = (const float*)d_in[1];
    const float* off_b = (const float*)d_in[2];
    const float* def_w = (const float*)d_in[3];
    const float* def_b = (const float*)d_in[4];
    float* out = (float*)d_out;

    cudaFuncSetAttribute(offset_mma_kernel, cudaFuncAttributeMaxDynamicSharedMemorySize,
                         OSM_TOTAL);                              // 73728 B
    cudaFuncSetAttribute(deform_kernel, cudaFuncAttributeMaxDynamicSharedMemorySize,
                         SM_TOTAL);                               // 40960 B

    prep_kernel<<<(GG*KK*CGc*CGc + 255) / 256, 256>>>(off_w, def_w);
    quad_kernel<<<BB*GG*CGc*HWs/256, 256>>>(x);
    offset_mma_kernel<<<BB*GG*(HH/4), 256, OSM_TOTAL>>>(x, off_b);
    deform_kernel<<<BB*GG*(HH/4), 256, SM_TOTAL>>>(def_b, out);
}

// round 17
// speedup vs baseline: 1.3055x; 1.0436x over previous
#include <cuda_runtime.h>
#include <cuda_bf16.h>
#include <cuda_fp16.h>
#include <math.h>
#include <stdint.h>

#define BB 16
#define GG 4
#define CGc 64
#define HH 64
#define WW 64
#define HWs 4096
#define KK 9

// ---------------- scratch (static; no allocation) ----------------
__device__ float g_off[BB*GG*18*HWs];                 // offsets [bg][c=2k+j][h][w]
__device__ float4 g_xQ[BB*GG*CGc*HWs];                // corner quads (268MB)
__device__ __nv_half g_wfh[GG*KK*CGc*CGc];            // def_w fp16, pre-SW128-swizzled rows [oc][ic]
__device__ __nv_bfloat16 g_owbh[GG*KK*32*CGc];        // off_w bf16 hi, SW128 rows [oc(32 pad)][ic]
__device__ __nv_bfloat16 g_owbl[GG*KK*32*CGc];        // off_w bf16 lo

#define SWZ128(off) ((off) ^ (((off) >> 3) & 0x70))

// ---------------- helpers ----------------
__device__ __forceinline__ uint32_t smem_u32(const void* p) {
    uint32_t a;
    asm("{ .reg .u64 t; cvta.to.shared.u64 t, %1; cvt.u32.u64 %0, t; }" : "=r"(a) : "l"(p));
    return a;
}
__device__ __forceinline__ void ldsm_x4(uint32_t* r, uint32_t addr) {
    asm volatile("ldmatrix.sync.aligned.m8n8.x4.shared.b16 {%0,%1,%2,%3}, [%4];"
        : "=r"(r[0]), "=r"(r[1]), "=r"(r[2]), "=r"(r[3]) : "r"(addr));
}
__device__ __forceinline__ void mma_bf16(float* d, const uint32_t* a, uint32_t b0, uint32_t b1) {
    asm volatile(
        "mma.sync.aligned.m16n8k16.row.col.f32.bf16.bf16.f32 "
        "{%0,%1,%2,%3}, {%4,%5,%6,%7}, {%8,%9}, {%0,%1,%2,%3};"
        : "+f"(d[0]), "+f"(d[1]), "+f"(d[2]), "+f"(d[3])
        : "r"(a[0]), "r"(a[1]), "r"(a[2]), "r"(a[3]), "r"(b0), "r"(b1));
}
__device__ __forceinline__ void mma_f16(float* d, const uint32_t* a, uint32_t b0, uint32_t b1) {
    asm volatile(
        "mma.sync.aligned.m16n8k16.row.col.f32.f16.f16.f32 "
        "{%0,%1,%2,%3}, {%4,%5,%6,%7}, {%8,%9}, {%0,%1,%2,%3};"
        : "+f"(d[0]), "+f"(d[1]), "+f"(d[2]), "+f"(d[3])
        : "r"(a[0]), "r"(a[1]), "r"(a[2]), "r"(a[3]), "r"(b0), "r"(b1));
}

// ---------------- prep: weight transforms ----------------
__global__ void prep_kernel(const float* __restrict__ off_w,
                            const float* __restrict__ def_w) {
    int idx = blockIdx.x * blockDim.x + threadIdx.x;
    const int n_w = GG*KK*CGc*CGc;    // 147456
    if (idx < n_w) {
        int ic = idx & 63;
        int oc = (idx >> 6) & 63;
        int gk = idx >> 12;           // g*9+k
        int k  = gk % KK;
        int g  = gk / KK;
        float w = def_w[((g*CGc + oc)*CGc + ic)*KK + k];
        uint32_t sw = SWZ128((uint32_t)(oc*128 + ic*2));
        size_t base = (size_t)(g*KK + k) * CGc * CGc;
        g_wfh[base + sw/2] = __float2half(w);
    }
    const int n_ow = GG*KK*32*CGc;    // 73728  offset-conv weights, oc padded to 32
    if (idx < n_ow) {
        int ic = idx & 63;
        int oc = (idx >> 6) & 31;
        int gk = idx >> 11;           // g*9+k
        int k  = gk % KK;
        int g  = gk / KK;
        float w = (oc < 18) ? off_w[((g*18 + oc)*CGc + ic)*KK + k] : 0.0f;
        __nv_bfloat16 hi = __float2bfloat16(w);
        float lo = w - __bfloat162float(hi);
        uint32_t sw = SWZ128((uint32_t)(oc*128 + ic*2));
        size_t base = (size_t)(g*KK + k) * 32 * CGc;
        g_owbh[base + sw/2] = hi;
        g_owbl[base + sw/2] = __float2bfloat16(lo);
    }
}

// ---------------- quad build: all 4 bilinear corners in one float4 ----------------
__global__ void __launch_bounds__(256) quad_kernel(const float* __restrict__ x) {
    size_t i = (size_t)blockIdx.x * 256 + threadIdx.x;   // over BB*GG*CGc*HWs
    int xc = (int)(i & 63);
    int yc = (int)((i >> 6) & 63);
    float v00 = x[i];
    float v01 = (xc < 63) ? x[i + 1]  : v00;
    float v10 = (yc < 63) ? x[i + 64] : v00;
    float v11 = (yc < 63) ? ((xc < 63) ? x[i + 65] : v10) : v01;
    g_xQ[i] = make_float4(v00, v01, v10, v11);
}

// ---------------- offset conv via mma.sync: 64 -> 18(pad 32), 3x3 (UNCHANGED bf16 3-term) ----------------
#define OSM_SHI  0
#define OSM_SLO  32768
#define OSM_WHI  65536
#define OSM_WLO  69632
#define OSM_TOTAL 73728

extern __shared__ char osmem[];
__global__ void __launch_bounds__(256) offset_mma_kernel(const float* __restrict__ x,
                                                         const float* __restrict__ off_b) {
    char* sm = osmem;
    uint32_t smem_base = smem_u32(sm);
    int tid  = threadIdx.x;
    int wid  = tid >> 5;
    int lane = tid & 31;

    int bid  = blockIdx.x;
    int hblk = bid & 15;
    int g    = (bid >> 4) & 3;
    int b    = bid >> 6;
    int bg   = b*GG + g;

    int m    = tid;
    int r    = m >> 6;
    int wpos = m & 63;
    int h    = hblk*4 + r;

    const float* xb = x + (size_t)bg * CGc * HWs;

    char* shi_row = sm + OSM_SHI + m*128;
    char* slo_row = sm + OSM_SLO + m*128;
    uint32_t swz = (uint32_t)((m & 7) << 4);

    float acc[2][4][4];
#pragma unroll
    for (int mt = 0; mt < 2; mt++)
#pragma unroll
        for (int nt = 0; nt < 4; nt++)
#pragma unroll
            for (int q = 0; q < 4; q++) acc[mt][nt][q] = 0.0f;

    int a_row0   = wid*32 + (lane & 15);
    int ab_colsl = (lane >> 4) << 4;
    int b_row0   = ((lane >> 3) & 1)*8 + (lane & 7);

    for (int k = 0; k < KK; k++) {
        {
            const uint4* s1 = (const uint4*)(g_owbh + (size_t)(g*KK + k) * 32 * CGc);
            const uint4* s2 = (const uint4*)(g_owbl + (size_t)(g*KK + k) * 32 * CGc);
            ((uint4*)(sm + OSM_WHI))[tid] = s1[tid];
            ((uint4*)(sm + OSM_WLO))[tid] = s2[tid];
        }

        int dy = k/3 - 1, dx = k%3 - 1;
        int y    = h + dy;
        int xcol = wpos + dx;
        bool valid = (y >= 0 && y < HH && xcol >= 0 && xcol < WW);
        const float* xs = xb + y*WW + xcol;
#pragma unroll
        for (int icp = 0; icp < 8; icp++) {
            uint32_t hp[4], lp[4];
#pragma unroll
            for (int jj = 0; jj < 2; jj++) {
                int ic = icp*8 + jj*4;
                float v0 = valid ? __ldg(xs + (size_t)(ic  )*HWs) : 0.0f;
                float v1 = valid ? __ldg(xs + (size_t)(ic+1)*HWs) : 0.0f;
                float v2 = valid ? __ldg(xs + (size_t)(ic+2)*HWs) : 0.0f;
                float v3 = valid ? __ldg(xs + (size_t)(ic+3)*HWs) : 0.0f;
                uint32_t hh0, hh1;
                asm("cvt.rn.bf16x2.f32 %0, %1, %2;" : "=r"(hh0) : "f"(v1), "f"(v0));
                asm("cvt.rn.bf16x2.f32 %0, %1, %2;" : "=r"(hh1) : "f"(v3), "f"(v2));
                float l0 = v0 - __uint_as_float(hh0 << 16);
                float l1 = v1 - __uint_as_float(hh0 & 0xffff0000u);
                float l2 = v2 - __uint_as_float(hh1 << 16);
                float l3 = v3 - __uint_as_float(hh1 & 0xffff0000u);
                uint32_t ll0, ll1;
                asm("cvt.rn.bf16x2.f32 %0, %1, %2;" : "=r"(ll0) : "f"(l1), "f"(l0));
                asm("cvt.rn.bf16x2.f32 %0, %1, %2;" : "=r"(ll1) : "f"(l3), "f"(l2));
                hp[2*jj] = hh0; hp[2*jj+1] = hh1;
                lp[2*jj] = ll0; lp[2*jj+1] = ll1;
            }
            uint32_t off = ((uint32_t)(icp*16)) ^ swz;
            *(uint4*)(shi_row + off) = make_uint4(hp[0], hp[1], hp[2], hp[3]);
            *(uint4*)(slo_row + off) = make_uint4(lp[0], lp[1], lp[2], lp[3]);
        }
        __syncthreads();

#pragma unroll
        for (int kc = 0; kc < 4; kc++) {
            int colb = kc*32 + ab_colsl;
            uint32_t ah[2][4], al[2][4];
#pragma unroll
            for (int mt = 0; mt < 2; mt++) {
                int row = a_row0 + mt*16;
                uint32_t boff = (uint32_t)(row*128 + (colb ^ ((row & 7) << 4)));
                ldsm_x4(ah[mt], smem_base + OSM_SHI + boff);
                ldsm_x4(al[mt], smem_base + OSM_SLO + boff);
            }
#pragma unroll
            for (int ntp = 0; ntp < 2; ntp++) {
                int nrow = b_row0 + ntp*16;
                uint32_t boff = (uint32_t)(nrow*128 + (colb ^ ((nrow & 7) << 4)));
                uint32_t bh[4], bl[4];
                ldsm_x4(bh, smem_base + OSM_WHI + boff);
                ldsm_x4(bl, smem_base + OSM_WLO + boff);
#pragma unroll
                for (int mt = 0; mt < 2; mt++) {
                    mma_bf16(acc[mt][2*ntp  ], ah[mt], bh[0], bh[2]);
                    mma_bf16(acc[mt][2*ntp  ], ah[mt], bl[0], bl[2]);
                    mma_bf16(acc[mt][2*ntp  ], al[mt], bh[0], bh[2]);
                    mma_bf16(acc[mt][2*ntp+1], ah[mt], bh[1], bh[3]);
                    mma_bf16(acc[mt][2*ntp+1], ah[mt], bl[1], bl[3]);
                    mma_bf16(acc[mt][2*ntp+1], al[mt], bh[1], bh[3]);
                }
            }
        }
        __syncthreads();
    }

    float* og = g_off + (size_t)bg * 18 * HWs + hblk*4*64;
    const float* obp = off_b + g*18;
#pragma unroll
    for (int mt = 0; mt < 2; mt++) {
        int row0  = wid*32 + mt*16 + (lane >> 2);
        int h_loc = row0 >> 6;
        int wp    = row0 & 63;
        float* p0 = og + h_loc*64 + wp;
        float* p1 = p0 + 8;
#pragma unroll
        for (int nt = 0; nt < 4; nt++) {
            int c0 = nt*8 + (lane & 3)*2;
            if (c0 < 18) {
                float bz0 = __ldg(obp + c0);
                float bz1 = __ldg(obp + c0 + 1);
                p0[(size_t)c0*HWs]     = acc[mt][nt][0] + bz0;
                p0[(size_t)(c0+1)*HWs] = acc[mt][nt][1] + bz1;
                p1[(size_t)c0*HWs]     = acc[mt][nt][2] + bz0;
                p1[(size_t)(c0+1)*HWs] = acc[mt][nt][3] + bz1;
            }
        }
    }
}

// ---------------- deformable conv: fp16 MMA, double-buffered tap pipeline ----------------
// block = (b, g, hblk of 4 rows); 256 threads (8 warps), 2 blocks/SM
// M=256 (4h x 64w), N=64 oc, K per tap = 64 ic, 9 taps
// iter k: gather tap k into buf(k&1); MMA tap k-1 from buf((k-1)&1); ONE barrier.
#define SM_S0  0         // S fp16 [256 x 64] SW128, buffer 0 : 32768 B
#define SM_S1  32768     // S buffer 1                        : 32768 B
#define SM_W0  65536     // W fp16 [64 x 64] SW128, buffer 0  :  8192 B
#define SM_W1  73728     // W buffer 1                        :  8192 B
#define SM_TOTAL 81920

extern __shared__ char smem2[];
__global__ void __launch_bounds__(256, 2) deform_kernel(const float* __restrict__ def_b,
                                                        float* __restrict__ out) {
    char* sm = smem2;
    uint32_t smem_base = smem_u32(sm);
    int tid  = threadIdx.x;
    int wid  = tid >> 5;
    int lane = tid & 31;

    int bid  = blockIdx.x;
    int hblk = bid & 15;
    int g    = (bid >> 4) & 3;
    int b    = bid >> 6;
    int bg   = b*GG + g;

    int m    = tid;            // S-tile row this thread gathers
    int r    = m >> 6;         // 0..3
    int wpos = m & 63;
    int h    = hblk*4 + r;

    const float4* xQb = g_xQ + (size_t)bg * CGc * HWs;
    const float* offp = g_off + (size_t)bg * 18 * HWs + h*64 + wpos;

    uint32_t swz = (uint32_t)((m & 7) << 4);

    float acc[2][8][4];
#pragma unroll
    for (int mt = 0; mt < 2; mt++)
#pragma unroll
        for (int nt = 0; nt < 8; nt++)
#pragma unroll
            for (int q = 0; q < 4; q++) acc[mt][nt][q] = 0.0f;

    int a_row0   = wid*32 + (lane & 15);
    int ab_colsl = (lane >> 4) << 4;
    int b_row0   = ((lane >> 3) & 1)*8 + (lane & 7);

    for (int k = 0; k <= KK; k++) {
        if (k < KK) {
            int buf = k & 1;
            // ---- W tile copy for tap k (pre-swizzled gmem, 8KB) ----
            {
                const uint4* s1 = (const uint4*)(g_wfh + (size_t)(g*KK + k) * CGc * CGc);
                uint4* d1 = (uint4*)(sm + SM_W0 + buf*8192);
                d1[tid]       = s1[tid];
                d1[tid + 256] = s1[tid + 256];
            }
            // ---- bilinear corner precompute ----
            float dy = __ldg(offp + (2*k    )*HWs);
            float dx = __ldg(offp + (2*k + 1)*HWs);
            float py = dy + (float)(k/3 - 1) + (float)h;
            float px = dx + (float)(k%3 - 1) + (float)wpos;
            float fy = floorf(py), fx = floorf(px);
            float wy = py - fy,    wx = px - fx;
            int y0 = (int)fy, x0 = (int)fx;
            int y1 = y0 + 1,  x1 = x0 + 1;
            float vy0 = (y0 >= 0 && y0 < HH) ? 1.f : 0.f;
            float vy1 = (y1 >= 0 && y1 < HH) ? 1.f : 0.f;
            float vx0 = (x0 >= 0 && x0 < WW) ? 1.f : 0.f;
            float vx1 = (x1 >= 0 && x1 < WW) ? 1.f : 0.f;
            float c00 = (1.f-wy)*(1.f-wx) * vy0 * vx0;
            float c01 = (1.f-wy)*wx       * vy0 * vx1;
            float c10 = wy*(1.f-wx)       * vy1 * vx0;
            float c11 = wy*wx             * vy1 * vx1;
            if (x0 < 0) { c00 = c01; c01 = 0.f; c10 = c11; c11 = 0.f; }
            if (y0 < 0) { c00 = c10; c01 = c11; c10 = 0.f; c11 = 0.f; }
            int xl = min(max(x0,0),WW-1);
            int yb = min(max(y0,0),HH-1);
            int o  = yb*WW + xl;

            // ---- gather (quad LDG.128) + fp16 convert into S[buf] ----
            char* s_row = sm + SM_S0 + buf*32768 + m*128;
#pragma unroll
            for (int icp = 0; icp < 8; icp++) {
                uint32_t hp[4];
#pragma unroll
                for (int jj = 0; jj < 2; jj++) {
                    int ic = icp*8 + jj*4;
                    float4 q0 = __ldg(xQb + (size_t)ic*HWs + o);
                    float4 q1 = __ldg(xQb + (size_t)(ic+1)*HWs + o);
                    float4 q2 = __ldg(xQb + (size_t)(ic+2)*HWs + o);
                    float4 q3 = __ldg(xQb + (size_t)(ic+3)*HWs + o);
                    float v0 = c00*q0.x + c01*q0.y + c10*q0.z + c11*q0.w;
                    float v1 = c00*q1.x + c01*q1.y + c10*q1.z + c11*q1.w;
                    float v2 = c00*q2.x + c01*q2.y + c10*q2.z + c11*q2.w;
                    float v3 = c00*q3.x + c01*q3.y + c10*q3.z + c11*q3.w;
                    uint32_t hh0, hh1;
                    asm("cvt.rn.f16x2.f32 %0, %1, %2;" : "=r"(hh0) : "f"(v1), "f"(v0));
                    asm("cvt.rn.f16x2.f32 %0, %1, %2;" : "=r"(hh1) : "f"(v3), "f"(v2));
                    hp[2*jj] = hh0; hp[2*jj+1] = hh1;
                }
                uint32_t off = ((uint32_t)(icp*16)) ^ swz;
                *(uint4*)(s_row + off) = make_uint4(hp[0], hp[1], hp[2], hp[3]);
            }
        }

        if (k > 0) {
            int pbuf = (k - 1) & 1;
            uint32_t sbase = smem_base + SM_S0 + pbuf*32768;
            uint32_t wbase = smem_base + SM_W0 + pbuf*8192;
            // ---- MMA: 4 k16-chunks x (2 m-tiles x 8 n-tiles), single fp16 term ----
#pragma unroll
            for (int kc = 0; kc < 4; kc++) {
                int colb = kc*32 + ab_colsl;
                uint32_t ah[2][4];
#pragma unroll
                for (int mt = 0; mt < 2; mt++) {
                    int row = a_row0 + mt*16;
                    uint32_t boff = (uint32_t)(row*128 + (colb ^ ((row & 7) << 4)));
                    ldsm_x4(ah[mt], sbase + boff);
                }
#pragma unroll
                for (int ntp = 0; ntp < 4; ntp++) {
                    int nrow = b_row0 + ntp*16;
                    uint32_t boff = (uint32_t)(nrow*128 + (colb ^ ((nrow & 7) << 4)));
                    uint32_t bh[4];
                    ldsm_x4(bh, wbase + boff);
#pragma unroll
                    for (int mt = 0; mt < 2; mt++) {
                        mma_f16(acc[mt][2*ntp  ], ah[mt], bh[0], bh[2]);
                        mma_f16(acc[mt][2*ntp+1], ah[mt], bh[1], bh[3]);
                    }
                }
            }
        }
        __syncthreads();
    }

    // ---- epilogue: fragment scatter to gmem (+bias) ----
    float* outg = out + (size_t)bg * CGc * HWs + hblk*4*64;
    const float* bbp = def_b + g*CGc;
#pragma unroll
    for (int mt = 0; mt < 2; mt++) {
        int row0  = wid*32 + mt*16 + (lane >> 2);
        int h_loc = row0 >> 6;
        int wp    = row0 & 63;
        float* p0 = outg + h_loc*64 + wp;
        float* p1 = p0 + 8;
#pragma unroll
        for (int nt = 0; nt < 8; nt++) {
            int oc0 = nt*8 + (lane & 3)*2;
            float bz0 = __ldg(bbp + oc0);
            float bz1 = __ldg(bbp + oc0 + 1);
            p0[(size_t)oc0*HWs]       = acc[mt][nt][0] + bz0;
            p0[(size_t)(oc0+1)*HWs]   = acc[mt][nt][1] + bz1;
            p1[(size_t)oc0*HWs]       = acc[mt][nt][2] + bz0;
            p1[(size_t)(oc0+1)*HWs]   = acc[mt][nt][3] + bz1;
        }
    }
}

// ---------------- launch ----------------
extern "C" void kernel_launch(void* const* d_in, const int* in_sizes, int n_in,
                              void* d_out, int out_size) {
    const float* x     = (const float*)d_in[0];
    const float* off_w = (const float*)d_in[1];
    const float* off_b = (const float*)d_in[2];
    const float* def_w = (const float*)d_in[3];
    const float* def_b = (const float*)d_in[4];
    float* out = (float*)d_out;

    cudaFuncSetAttribute(offset_mma_kernel, cudaFuncAttributeMaxDynamicSharedMemorySize,
                         OSM_TOTAL);                              // 73728 B
    cudaFuncSetAttribute(deform_kernel, cudaFuncAttributeMaxDynamicSharedMemorySize,
                         SM_TOTAL);                               // 81920 B

    prep_kernel<<<(GG*KK*CGc*CGc + 255) / 256, 256>>>(off_w, def_w);
    quad_kernel<<<BB*GG*CGc*HWs/256, 256>>>(x);
    offset_mma_kernel<<<BB*GG*(HH/4), 256, OSM_TOTAL>>>(x, off_b);
    deform_kernel<<<BB*GG*(HH/4), 256, SM_TOTAL>>>(def_b, out);
}